// round 10
// baseline (speedup 1.0000x reference)
#include <cuda_runtime.h>
#include <cstdint>

// Problem constants
#define T_DIM 1024
#define B_DIM 4
#define S_DIM 1024
#define E_DIM 1024
#define H_DIM 16
#define D_DIM 64
#define TB (T_DIM * B_DIM)
#define BE (B_DIM * E_DIM)

// Scratch (device globals — no allocation allowed)
__device__ float g_Q[TB * E_DIM];
__device__ float g_K[TB * E_DIM];
__device__ float g_V[TB * E_DIM];
__device__ float g_Ctx[TB * E_DIM];
__device__ float g_P[(long)B_DIM * H_DIM * T_DIM * S_DIM];   // scores -> probs (256 MB)

// ---------------------------------------------------------------------------
// tf32 helpers
// ---------------------------------------------------------------------------
__device__ __forceinline__ uint32_t f2tf(float x) {
    uint32_t r;
    asm("cvt.rna.tf32.f32 %0, %1;" : "=r"(r) : "f"(x));
    return r;
}

__device__ __forceinline__ void mma8(float* d, const uint32_t* a, const uint32_t* b) {
    asm volatile(
        "mma.sync.aligned.m16n8k8.row.col.f32.tf32.tf32.f32 "
        "{%0,%1,%2,%3}, {%4,%5,%6,%7}, {%8,%9}, {%0,%1,%2,%3};\n"
        : "+f"(d[0]), "+f"(d[1]), "+f"(d[2]), "+f"(d[3])
        : "r"(a[0]), "r"(a[1]), "r"(a[2]), "r"(a[3]), "r"(b[0]), "r"(b[1]));
}

#define PBK 32
#define LDA 132

// ---------------------------------------------------------------------------
// Fragment-interleaved layout (validated in R9):
// A word = ((sb*numMb + mb)*32 + (m%8)*4 + (k%4))*4 + ((k%8)>=4)*2 + ((m%16)>=8)
// B word = ((sb*numNb8 + nb8)*32 + (n%8)*4 + (k%4))*2 + ((k%8)>=4)
// Mainloop: a-frag = 1 LDS.128, b-frag = 1 LDS.64.
// ---------------------------------------------------------------------------
#define GEMM_SMEM_WORDS 16384
#define GEMM_SMEM_BYTES (GEMM_SMEM_WORDS * 4)   // 65536

#define GEMM_STAGE(DSTA, DSTB, PA, PW)                                        \
    _Pragma("unroll")                                                         \
    for (int p = 0; p < 4; p++) {                                             \
        int row = lrow + p * 32;                                              \
        int mbq = row >> 4, fragm = ((row & 15) >= 8) ? 1 : 0;                \
        int nb8 = row >> 3;                                                   \
        int laneb = (row & 7) * 4;                                            \
        uint32_t* aw = (DSTA) + ((sbq * 8 + mbq) * 32 + laneb) * 4 + fragk2 + fragm; \
        uint32_t* bw = (DSTB) + ((sbq * 16 + nb8) * 32 + laneb) * 2 + fragb;  \
        aw[0]  = f2tf((PA)[p].x); aw[4]  = f2tf((PA)[p].y);                   \
        aw[8]  = f2tf((PA)[p].z); aw[12] = f2tf((PA)[p].w);                   \
        bw[0]  = f2tf((PW)[p].x); bw[2]  = f2tf((PW)[p].y);                   \
        bw[4]  = f2tf((PW)[p].z); bw[6]  = f2tf((PW)[p].w);                   \
    }

#define GEMM_DB_CORE(APTR, WPTR)                                              \
    const int lrow = tid >> 3, lkc = (tid & 7) << 2;                          \
    const int sbq = lkc >> 3;                                                 \
    const int fragk2 = ((lkc & 7) >= 4) ? 2 : 0;                              \
    const int fragb  = ((lkc & 7) >= 4) ? 1 : 0;                              \
    float4 pa[4], pw[4];                                                      \
    _Pragma("unroll")                                                         \
    for (int p = 0; p < 4; p++) {                                             \
        int row = lrow + p * 32;                                              \
        pa[p] = *(const float4*)((APTR) + (long)(m0 + row) * E_DIM + lkc);    \
        pw[p] = *(const float4*)((WPTR) + (long)(n0 + row) * E_DIM + lkc);    \
    }                                                                         \
    GEMM_STAGE(As, Bs, pa, pw)                                                \
    for (int it = 0; it < E_DIM / PBK; it++) {                                \
        const int cur = (it & 1) * 4096;                                      \
        __syncthreads();                                                      \
        if (it < E_DIM / PBK - 1) {                                           \
            int k0 = (it + 1) * PBK;                                          \
            _Pragma("unroll")                                                 \
            for (int p = 0; p < 4; p++) {                                     \
                int row = lrow + p * 32;                                      \
                pa[p] = *(const float4*)((APTR) + (long)(m0 + row) * E_DIM + k0 + lkc); \
                pw[p] = *(const float4*)((WPTR) + (long)(n0 + row) * E_DIM + k0 + lkc); \
            }                                                                 \
        }                                                                     \
        const uint32_t* Acur = As + cur;                                      \
        const uint32_t* Bcur = Bs + cur;                                      \
        _Pragma("unroll")                                                     \
        for (int sb = 0; sb < 4; sb++) {                                      \
            uint4 af[4];                                                      \
            uint2 bf[4];                                                      \
            _Pragma("unroll")                                                 \
            for (int mt = 0; mt < 4; mt++)                                    \
                af[mt] = *(const uint4*)(Acur + ((sb * 8 + wmb + mt) * 32 + lane) * 4); \
            _Pragma("unroll")                                                 \
            for (int nt = 0; nt < 4; nt++)                                    \
                bf[nt] = *(const uint2*)(Bcur + ((sb * 16 + wnb + nt) * 32 + lane) * 2); \
            _Pragma("unroll")                                                 \
            for (int mt = 0; mt < 4; mt++)                                    \
                _Pragma("unroll")                                             \
                for (int nt = 0; nt < 4; nt++)                                \
                    mma8(acc[mt][nt], (const uint32_t*)&af[mt], (const uint32_t*)&bf[nt]); \
        }                                                                     \
        if (it < E_DIM / PBK - 1) {                                           \
            const int nxt = ((it + 1) & 1) * 4096;                            \
            GEMM_STAGE(As + nxt, Bs + nxt, pa, pw)                            \
        }                                                                     \
    }

#define GEMM_PROLOGUE                                                         \
    extern __shared__ uint32_t dsm[];                                         \
    uint32_t* As = dsm;                                                       \
    uint32_t* Bs = dsm + 8192;                                                \
    const int tid = threadIdx.x, lane = tid & 31, wid = tid >> 5;             \
    const int wm = (wid >> 2) * 64, wn = (wid & 3) * 32;                      \
    const int wmb = wm >> 4, wnb = wn >> 3;                                   \
    const int g = lane >> 2, tg = lane & 3;                                   \
    float acc[4][4][4];                                                       \
    _Pragma("unroll")                                                         \
    for (int i = 0; i < 4; i++)                                               \
        _Pragma("unroll")                                                     \
        for (int j = 0; j < 4; j++)                                           \
            _Pragma("unroll")                                                 \
            for (int q = 0; q < 4; q++) acc[i][j][q] = 0.f;

#define GEMM_EPILOGUE(CPTR, BIASPTR, ALPHA)                                   \
    _Pragma("unroll")                                                         \
    for (int mt = 0; mt < 4; mt++) {                                          \
        int r0 = m0 + wm + mt * 16 + g;                                       \
        _Pragma("unroll")                                                     \
        for (int nt = 0; nt < 4; nt++) {                                      \
            int c = n0 + wn + nt * 8 + 2 * tg;                                \
            float2 bv = *(const float2*)((BIASPTR) + c);                      \
            float2 o0, o1;                                                    \
            o0.x = (ALPHA) * (acc[mt][nt][0] + bv.x);                         \
            o0.y = (ALPHA) * (acc[mt][nt][1] + bv.y);                         \
            o1.x = (ALPHA) * (acc[mt][nt][2] + bv.x);                         \
            o1.y = (ALPHA) * (acc[mt][nt][3] + bv.y);                         \
            *(float2*)((CPTR) + (long)r0 * E_DIM + c) = o0;                   \
            *(float2*)((CPTR) + (long)(r0 + 8) * E_DIM + c) = o1;             \
        }                                                                     \
    }

// ---------------------------------------------------------------------------
// Merged QKV projection: grid (24, 32); seg = blockIdx.x>>3 picks q/k/v.
// ---------------------------------------------------------------------------
__global__ void __launch_bounds__(256) gemm_qkv(
    const float* __restrict__ query, const float* __restrict__ key,
    const float* __restrict__ value, const float* __restrict__ ipw,
    const float* __restrict__ ipb,
    float* __restrict__ Qo, float* __restrict__ Ko, float* __restrict__ Vo)
{
    GEMM_PROLOGUE
    const int m0 = blockIdx.y * 128;
    const int seg = blockIdx.x >> 3;
    const int n0 = (blockIdx.x & 7) * 128;

    const float* A = (seg == 0) ? query : (seg == 1) ? key : value;
    const float* W = ipw + (long)seg * E_DIM * E_DIM;
    const float* bias = ipb + seg * E_DIM;
    float* C = (seg == 0) ? Qo : (seg == 1) ? Ko : Vo;
    const float alpha = (seg == 0) ? 0.125f : 1.0f;

    GEMM_DB_CORE(A, W)
    GEMM_EPILOGUE(C, bias, alpha)
}

// ---------------------------------------------------------------------------
// Output projection
// ---------------------------------------------------------------------------
__global__ void __launch_bounds__(256) gemm_out(
    const float* __restrict__ Ain, const float* __restrict__ W,
    const float* __restrict__ bias, float* __restrict__ C)
{
    GEMM_PROLOGUE
    const int m0 = blockIdx.y * 128, n0 = blockIdx.x * 128;

    GEMM_DB_CORE(Ain, W)
    GEMM_EPILOGUE(C, bias, 1.0f)
}

// ---------------------------------------------------------------------------
// Score kernel, fragment-interleaved: scores[z][T,S] = Q K^T + masks.
// 128x128 tile, K=64 staged once. A: 8 slabs x 8 mb (8192 w);
// B: 8 slabs x 16 nb8 (8192 w). 64KB dynamic smem, single sync.
// ---------------------------------------------------------------------------
#define SCORE_SMEM_BYTES (16384 * 4)

__global__ void __launch_bounds__(256) score_kernel(
    const float* __restrict__ Q, const float* __restrict__ Kx,
    const float* __restrict__ amask, const int* __restrict__ pad,
    float* __restrict__ Sc)
{
    extern __shared__ uint32_t dsm[];
    uint32_t* As = dsm;                 // 8192 words
    uint32_t* Bs = dsm + 8192;          // 8192 words
    const int tid = threadIdx.x, lane = tid & 31, wid = tid >> 5;
    const int wm = (wid >> 2) * 64, wn = (wid & 3) * 32;
    const int wmb = wm >> 4, wnb = wn >> 3;
    const int t0 = blockIdx.y * 128, s0 = blockIdx.x * 128;
    const int z = blockIdx.z;
    const int b = z >> 4, h = z & 15;
    const int g = lane >> 2, tg = lane & 3;
    const float* Qb = Q + (long)b * E_DIM + h * D_DIM;
    const float* Kb = Kx + (long)b * E_DIM + h * D_DIM;

    float acc[4][4][4];
    #pragma unroll
    for (int i = 0; i < 4; i++)
        #pragma unroll
        for (int j = 0; j < 4; j++)
            #pragma unroll
            for (int q = 0; q < 4; q++) acc[i][j][q] = 0.f;

    // stage: 8 threads/row, rows srow + pr*32, k-float4s skc and skc+32
    {
        const int srow = tid >> 3, skc = (tid & 7) << 2;
        const int ssb = skc >> 3;
        const int sfragk2 = ((skc & 7) >= 4) ? 2 : 0;
        const int sfragb  = ((skc & 7) >= 4) ? 1 : 0;
        #pragma unroll
        for (int pr = 0; pr < 4; pr++) {
            int row = srow + pr * 32;
            int mb = row >> 4, fragm = ((row & 15) >= 8) ? 1 : 0;
            int nb8 = row >> 3;
            int lanep = (row & 7) * 4;
            #pragma unroll
            for (int pk = 0; pk < 2; pk++) {
                int kc = skc + pk * 32;
                int sb = ssb + pk * 4;
                float4 q4 = *(const float4*)(Qb + (long)(t0 + row) * BE + kc);
                float4 k4 = *(const float4*)(Kb + (long)(s0 + row) * BE + kc);
                uint32_t* aw = As + ((sb * 8 + mb) * 32 + lanep) * 4 + sfragk2 + fragm;
                uint32_t* bw = Bs + ((sb * 16 + nb8) * 32 + lanep) * 2 + sfragb;
                aw[0]  = f2tf(q4.x); aw[4]  = f2tf(q4.y);
                aw[8]  = f2tf(q4.z); aw[12] = f2tf(q4.w);
                bw[0]  = f2tf(k4.x); bw[2]  = f2tf(k4.y);
                bw[4]  = f2tf(k4.z); bw[6]  = f2tf(k4.w);
            }
        }
    }
    __syncthreads();

    #pragma unroll
    for (int sb = 0; sb < 8; sb++) {
        uint4 af[4];
        uint2 bf[4];
        #pragma unroll
        for (int mt = 0; mt < 4; mt++)
            af[mt] = *(const uint4*)(As + ((sb * 8 + wmb + mt) * 32 + lane) * 4);
        #pragma unroll
        for (int nt = 0; nt < 4; nt++)
            bf[nt] = *(const uint2*)(Bs + ((sb * 16 + wnb + nt) * 32 + lane) * 2);
        #pragma unroll
        for (int mt = 0; mt < 4; mt++)
            #pragma unroll
            for (int nt = 0; nt < 4; nt++)
                mma8(acc[mt][nt], (const uint32_t*)&af[mt], (const uint32_t*)&bf[nt]);
    }

    float* So = Sc + (long)z * T_DIM * S_DIM;
    #pragma unroll
    for (int mt = 0; mt < 4; mt++) {
        int t = t0 + wm + mt * 16 + g;
        #pragma unroll
        for (int nt = 0; nt < 4; nt++) {
            int s = s0 + wn + nt * 8 + 2 * tg;
            float p0 = pad[b * S_DIM + s]     ? -1e30f : 0.f;
            float p1 = pad[b * S_DIM + s + 1] ? -1e30f : 0.f;
            float2 a0 = *(const float2*)(amask + (long)t * S_DIM + s);
            float2 a1 = *(const float2*)(amask + (long)(t + 8) * S_DIM + s);
            float2 o0, o1;
            o0.x = acc[mt][nt][0] + a0.x + p0;
            o0.y = acc[mt][nt][1] + a0.y + p1;
            o1.x = acc[mt][nt][2] + a1.x + p0;
            o1.y = acc[mt][nt][3] + a1.y + p1;
            *(float2*)(So + (long)t * S_DIM + s) = o0;
            *(float2*)(So + (long)(t + 8) * S_DIM + s) = o1;
        }
    }
}

// ---------------------------------------------------------------------------
// Softmax + head-average (verbatim): block = (b,t), 16 warps = 16 heads.
// ---------------------------------------------------------------------------
#define SA_SMEM_BYTES (H_DIM * S_DIM * 4)   // 65536

__global__ void __launch_bounds__(512) softmax_avg(
    float* __restrict__ P, float* __restrict__ avgw)
{
    extern __shared__ float Ps[];            // [16][1024]
    const int bid = blockIdx.x;
    const int b = bid >> 10, t = bid & 1023;
    const int h = threadIdx.x >> 5, lane = threadIdx.x & 31;

    float4* p = (float4*)(P + (((long)(b * H_DIM + h) * T_DIM) + t) * S_DIM);
    float4 v[8];
    float m = -1e30f;
    #pragma unroll
    for (int i = 0; i < 8; i++) {
        v[i] = p[lane + 32 * i];
        m = fmaxf(m, fmaxf(fmaxf(v[i].x, v[i].y), fmaxf(v[i].z, v[i].w)));
    }
    #pragma unroll
    for (int o = 16; o; o >>= 1) m = fmaxf(m, __shfl_xor_sync(0xffffffffu, m, o));
    float sum = 0.f;
    #pragma unroll
    for (int i = 0; i < 8; i++) {
        v[i].x = __expf(v[i].x - m); v[i].y = __expf(v[i].y - m);
        v[i].z = __expf(v[i].z - m); v[i].w = __expf(v[i].w - m);
        sum += v[i].x + v[i].y + v[i].z + v[i].w;
    }
    #pragma unroll
    for (int o = 16; o; o >>= 1) sum += __shfl_xor_sync(0xffffffffu, sum, o);
    float inv = 1.0f / sum;
    float4* ps = (float4*)(Ps + h * S_DIM);
    #pragma unroll
    for (int i = 0; i < 8; i++) {
        v[i].x *= inv; v[i].y *= inv; v[i].z *= inv; v[i].w *= inv;
        p[lane + 32 * i] = v[i];
        ps[lane + 32 * i] = v[i];
    }
    __syncthreads();

    int s2 = threadIdx.x * 2;
    float a0 = 0.f, a1 = 0.f;
    #pragma unroll
    for (int hh = 0; hh < H_DIM; hh++) {
        float2 pv = *(const float2*)(Ps + hh * S_DIM + s2);
        a0 += pv.x; a1 += pv.y;
    }
    const float inv16 = 1.0f / H_DIM;
    *(float2*)(avgw + ((long)b * T_DIM + t) * S_DIM + s2) =
        make_float2(a0 * inv16, a1 * inv16);
}

// ---------------------------------------------------------------------------
// PV, fragment-interleaved + double-buffered: Ctx[b,h] = P[z] @ V[b,h].
// Per stage: A = 4 slabs x 8 mb (4096 w), B = 4 slabs x 8 nb8 (2048 w).
// Layout: [A0|A1|B0|B1] -> 12288 words = 48KB.
// ---------------------------------------------------------------------------
#define PV_SMEM_BYTES (12288 * 4)   // 49152

__global__ void __launch_bounds__(256) pv_kernel(
    const float* __restrict__ Sc, const float* __restrict__ V,
    float* __restrict__ Ctx)
{
    extern __shared__ uint32_t dsm[];
    uint32_t* Asm = dsm;            // 2 stages x 4096
    uint32_t* Bsm = dsm + 8192;     // 2 stages x 2048
    const int tid = threadIdx.x, lane = tid & 31, wid = tid >> 5;
    const int wm = (wid >> 1) * 32, wn = (wid & 1) * 32;
    const int wmb = wm >> 4, wnb = wn >> 3;
    const int t0 = blockIdx.x * 128;
    const int z = blockIdx.z;
    const int b = z >> 4, h = z & 15;
    const int g = lane >> 2, tg = lane & 3;
    const float* Pb = Sc + (long)z * T_DIM * S_DIM;
    const float* Vb = V + (long)b * E_DIM + h * D_DIM;

    float acc[2][4][4];
    #pragma unroll
    for (int i = 0; i < 2; i++)
        #pragma unroll
        for (int j = 0; j < 4; j++)
            #pragma unroll
            for (int q = 0; q < 4; q++) acc[i][j][q] = 0.f;

    // A staging indices: rows arow + p*32, k-float4 at akc
    const int arow = tid >> 3, akc = (tid & 7) << 2;
    const int asb = akc >> 3;
    const int afragk2 = ((akc & 7) >= 4) ? 2 : 0;
    // B staging indices: k-rows bs_s + p*16, n-float4 at bs_d
    const int bs_s = tid >> 4, bs_d = (tid & 15) << 2;
    const int bnb8 = bs_d >> 3;
    const int bnmod4 = (bs_d & 7) * 4;

    float4 pa[4], pv[2];
    #pragma unroll
    for (int p = 0; p < 4; p++)
        pa[p] = *(const float4*)(Pb + (long)(t0 + arow + p * 32) * S_DIM + akc);
    #pragma unroll
    for (int p = 0; p < 2; p++)
        pv[p] = *(const float4*)(Vb + (long)(bs_s + p * 16) * BE + bs_d);

#define PV_STAGE(ADST, BDST)                                                  \
    _Pragma("unroll")                                                         \
    for (int p = 0; p < 4; p++) {                                             \
        int row = arow + p * 32;                                              \
        int mb = row >> 4, fragm = ((row & 15) >= 8) ? 1 : 0;                 \
        uint32_t* aw = (ADST) + ((asb * 8 + mb) * 32 + (row & 7) * 4) * 4 + afragk2 + fragm; \
        aw[0]  = f2tf(pa[p].x); aw[4]  = f2tf(pa[p].y);                       \
        aw[8]  = f2tf(pa[p].z); aw[12] = f2tf(pa[p].w);                       \
    }                                                                         \
    _Pragma("unroll")                                                         \
    for (int p = 0; p < 2; p++) {                                             \
        int s = bs_s + p * 16;                                                \
        int sb = s >> 3;                                                      \
        int fb = ((s & 7) >= 4) ? 1 : 0;                                      \
        uint32_t* bw = (BDST) + ((sb * 8 + bnb8) * 32 + bnmod4 + (s & 3)) * 2 + fb; \
        bw[0]  = f2tf(pv[p].x); bw[8]  = f2tf(pv[p].y);                       \
        bw[16] = f2tf(pv[p].z); bw[24] = f2tf(pv[p].w);                       \
    }

    PV_STAGE(Asm, Bsm)

    for (int it = 0; it < S_DIM / PBK; it++) {
        const uint32_t* Acur = Asm + (it & 1) * 4096;
        const uint32_t* Bcur = Bsm + (it & 1) * 2048;
        __syncthreads();
        if (it < S_DIM / PBK - 1) {
            int k0 = (it + 1) * PBK;
            #pragma unroll
            for (int p = 0; p < 4; p++)
                pa[p] = *(const float4*)(Pb + (long)(t0 + arow + p * 32) * S_DIM + k0 + akc);
            #pragma unroll
            for (int p = 0; p < 2; p++)
                pv[p] = *(const float4*)(Vb + (long)(k0 + bs_s + p * 16) * BE + bs_d);
        }
        #pragma unroll
        for (int sb = 0; sb < 4; sb++) {
            uint4 af[2];
            uint2 bf[4];
            #pragma unroll
            for (int mt = 0; mt < 2; mt++)
                af[mt] = *(const uint4*)(Acur + ((sb * 8 + wmb + mt) * 32 + lane) * 4);
            #pragma unroll
            for (int nt = 0; nt < 4; nt++)
                bf[nt] = *(const uint2*)(Bcur + ((sb * 8 + wnb + nt) * 32 + lane) * 2);
            #pragma unroll
            for (int mt = 0; mt < 2; mt++)
                #pragma unroll
                for (int nt = 0; nt < 4; nt++)
                    mma8(acc[mt][nt], (const uint32_t*)&af[mt], (const uint32_t*)&bf[nt]);
        }
        if (it < S_DIM / PBK - 1) {
            uint32_t* Anxt = Asm + ((it + 1) & 1) * 4096;
            uint32_t* Bnxt = Bsm + ((it + 1) & 1) * 2048;
            PV_STAGE(Anxt, Bnxt)
        }
    }

    #pragma unroll
    for (int mt = 0; mt < 2; mt++) {
        int t = t0 + wm + mt * 16 + g;
        #pragma unroll
        for (int nt = 0; nt < 4; nt++) {
            int d = wn + nt * 8 + 2 * tg;
            *(float2*)(Ctx + (long)t * BE + b * E_DIM + h * D_DIM + d) =
                make_float2(acc[mt][nt][0], acc[mt][nt][1]);
            *(float2*)(Ctx + (long)(t + 8) * BE + b * E_DIM + h * D_DIM + d) =
                make_float2(acc[mt][nt][2], acc[mt][nt][3]);
        }
    }
}

// ---------------------------------------------------------------------------
extern "C" void kernel_launch(void* const* d_in, const int* in_sizes, int n_in,
                              void* d_out, int out_size) {
    const float* query = (const float*)d_in[0];
    const float* key   = (const float*)d_in[1];
    const float* value = (const float*)d_in[2];
    const int*   pad   = (const int*)d_in[3];
    const float* amask = (const float*)d_in[4];
    const float* ipw   = (const float*)d_in[5];
    const float* ipb   = (const float*)d_in[6];
    const float* ow    = (const float*)d_in[7];
    const float* ob    = (const float*)d_in[8];

    float* out  = (float*)d_out;
    float* avgw = out + (long)T_DIM * B_DIM * E_DIM;

    float *Qp, *Kp, *Vp, *Cp, *Pp;
    cudaGetSymbolAddress((void**)&Qp, g_Q);
    cudaGetSymbolAddress((void**)&Kp, g_K);
    cudaGetSymbolAddress((void**)&Vp, g_V);
    cudaGetSymbolAddress((void**)&Cp, g_Ctx);
    cudaGetSymbolAddress((void**)&Pp, g_P);

    cudaFuncSetAttribute(gemm_qkv,
        cudaFuncAttributeMaxDynamicSharedMemorySize, GEMM_SMEM_BYTES);
    cudaFuncSetAttribute(gemm_out,
        cudaFuncAttributeMaxDynamicSharedMemorySize, GEMM_SMEM_BYTES);
    cudaFuncSetAttribute(score_kernel,
        cudaFuncAttributeMaxDynamicSharedMemorySize, SCORE_SMEM_BYTES);
    cudaFuncSetAttribute(softmax_avg,
        cudaFuncAttributeMaxDynamicSharedMemorySize, SA_SMEM_BYTES);
    cudaFuncSetAttribute(pv_kernel,
        cudaFuncAttributeMaxDynamicSharedMemorySize, PV_SMEM_BYTES);

    gemm_qkv<<<dim3(24, 32), 256, GEMM_SMEM_BYTES>>>(
        query, key, value, ipw, ipb, Qp, Kp, Vp);

    score_kernel<<<dim3(8, 8, 64), 256, SCORE_SMEM_BYTES>>>(
        Qp, Kp, amask, pad, Pp);

    softmax_avg<<<B_DIM * T_DIM, 512, SA_SMEM_BYTES>>>(Pp, avgw);

    pv_kernel<<<dim3(8, 1, 64), 256, PV_SMEM_BYTES>>>(Pp, Vp, Cp);

    gemm_out<<<dim3(8, 32), 256, GEMM_SMEM_BYTES>>>(Cp, ow, ob, out);
}

// round 11
// speedup vs baseline: 1.3085x; 1.3085x over previous
#include <cuda_runtime.h>
#include <cstdint>

// Problem constants
#define T_DIM 1024
#define B_DIM 4
#define S_DIM 1024
#define E_DIM 1024
#define H_DIM 16
#define D_DIM 64
#define TB (T_DIM * B_DIM)
#define BE (B_DIM * E_DIM)

// Scratch (device globals — no allocation allowed)
__device__ float g_Q[TB * E_DIM];
__device__ float g_K[TB * E_DIM];
__device__ float g_V[TB * E_DIM];
__device__ float g_Ctx[TB * E_DIM];
__device__ float g_P[(long)B_DIM * H_DIM * T_DIM * S_DIM];   // scores -> probs (256 MB)

// ---------------------------------------------------------------------------
// tf32 helpers
// ---------------------------------------------------------------------------
__device__ __forceinline__ uint32_t f2tf(float x) {
    uint32_t r;
    asm("cvt.rna.tf32.f32 %0, %1;" : "=r"(r) : "f"(x));
    return r;
}

__device__ __forceinline__ void mma8(float* d, const uint32_t* a, const uint32_t* b) {
    asm volatile(
        "mma.sync.aligned.m16n8k8.row.col.f32.tf32.tf32.f32 "
        "{%0,%1,%2,%3}, {%4,%5,%6,%7}, {%8,%9}, {%0,%1,%2,%3};\n"
        : "+f"(d[0]), "+f"(d[1]), "+f"(d[2]), "+f"(d[3])
        : "r"(a[0]), "r"(a[1]), "r"(a[2]), "r"(a[3]), "r"(b[0]), "r"(b[1]));
}

#define PBK 32
#define LDA 132

// ---------------------------------------------------------------------------
// Fragment-interleaved layout (R9) + staging swizzle (this round):
// element (k,m) stored at slot (m%8)*4 + ((k%4 + m + slab)&3); sub-word =
// ((k%8)>=4)*2 + ((m%16)>=8) for A, ((k%8)>=4) for B.
// Loads: slot = g*4 + ((tg + g + sb)&3) — one LDS.128 (A) / LDS.64 (B).
// Staging STS conflicts: A 8-way -> 2-way, B 8-way -> conflict-free.
// ---------------------------------------------------------------------------
#define GEMM_SMEM_WORDS 16384
#define GEMM_SMEM_BYTES (GEMM_SMEM_WORDS * 4)   // 65536

#define GEMM_STAGE(DSTA, DSTB, PA, PW)                                        \
    _Pragma("unroll")                                                         \
    for (int p = 0; p < 4; p++) {                                             \
        int row = lrow + p * 32;                                              \
        int mbq = row >> 4, fragm = ((row & 15) >= 8) ? 1 : 0;                \
        int nb8 = row >> 3;                                                   \
        int laneb = (row & 7) * 4;                                            \
        int R = (row + sbq) & 3;                                              \
        uint32_t* aw = (DSTA) + ((sbq * 8 + mbq) * 32 + laneb) * 4 + fragk2 + fragm; \
        uint32_t* bw = (DSTB) + ((sbq * 16 + nb8) * 32 + laneb) * 2 + fragb;  \
        aw[4 * ((0 + R) & 3)] = f2tf((PA)[p].x);                              \
        aw[4 * ((1 + R) & 3)] = f2tf((PA)[p].y);                              \
        aw[4 * ((2 + R) & 3)] = f2tf((PA)[p].z);                              \
        aw[4 * ((3 + R) & 3)] = f2tf((PA)[p].w);                              \
        bw[2 * ((0 + R) & 3)] = f2tf((PW)[p].x);                              \
        bw[2 * ((1 + R) & 3)] = f2tf((PW)[p].y);                              \
        bw[2 * ((2 + R) & 3)] = f2tf((PW)[p].z);                              \
        bw[2 * ((3 + R) & 3)] = f2tf((PW)[p].w);                              \
    }

#define GEMM_DB_CORE(APTR, WPTR)                                              \
    const int lrow = tid >> 3, lkc = (tid & 7) << 2;                          \
    const int sbq = lkc >> 3;                                                 \
    const int fragk2 = ((lkc & 7) >= 4) ? 2 : 0;                              \
    const int fragb  = ((lkc & 7) >= 4) ? 1 : 0;                              \
    float4 pa[4], pw[4];                                                      \
    _Pragma("unroll")                                                         \
    for (int p = 0; p < 4; p++) {                                             \
        int row = lrow + p * 32;                                              \
        pa[p] = *(const float4*)((APTR) + (long)(m0 + row) * E_DIM + lkc);    \
        pw[p] = *(const float4*)((WPTR) + (long)(n0 + row) * E_DIM + lkc);    \
    }                                                                         \
    GEMM_STAGE(As, Bs, pa, pw)                                                \
    for (int it = 0; it < E_DIM / PBK; it++) {                                \
        const int cur = (it & 1) * 4096;                                      \
        __syncthreads();                                                      \
        if (it < E_DIM / PBK - 1) {                                           \
            int k0 = (it + 1) * PBK;                                          \
            _Pragma("unroll")                                                 \
            for (int p = 0; p < 4; p++) {                                     \
                int row = lrow + p * 32;                                      \
                pa[p] = *(const float4*)((APTR) + (long)(m0 + row) * E_DIM + k0 + lkc); \
                pw[p] = *(const float4*)((WPTR) + (long)(n0 + row) * E_DIM + k0 + lkc); \
            }                                                                 \
        }                                                                     \
        const uint32_t* Acur = As + cur;                                      \
        const uint32_t* Bcur = Bs + cur;                                      \
        _Pragma("unroll")                                                     \
        for (int sb = 0; sb < 4; sb++) {                                      \
            const int sw = (g << 2) + ((tg + g + sb) & 3);                    \
            uint4 af[4];                                                      \
            uint2 bf[4];                                                      \
            _Pragma("unroll")                                                 \
            for (int mt = 0; mt < 4; mt++)                                    \
                af[mt] = *(const uint4*)(Acur + ((sb * 8 + wmb + mt) * 32 + sw) * 4); \
            _Pragma("unroll")                                                 \
            for (int nt = 0; nt < 4; nt++)                                    \
                bf[nt] = *(const uint2*)(Bcur + ((sb * 16 + wnb + nt) * 32 + sw) * 2); \
            _Pragma("unroll")                                                 \
            for (int mt = 0; mt < 4; mt++)                                    \
                _Pragma("unroll")                                             \
                for (int nt = 0; nt < 4; nt++)                                \
                    mma8(acc[mt][nt], (const uint32_t*)&af[mt], (const uint32_t*)&bf[nt]); \
        }                                                                     \
        if (it < E_DIM / PBK - 1) {                                           \
            const int nxt = ((it + 1) & 1) * 4096;                            \
            GEMM_STAGE(As + nxt, Bs + nxt, pa, pw)                            \
        }                                                                     \
    }

#define GEMM_PROLOGUE                                                         \
    extern __shared__ uint32_t dsm[];                                         \
    uint32_t* As = dsm;                                                       \
    uint32_t* Bs = dsm + 8192;                                                \
    const int tid = threadIdx.x, lane = tid & 31, wid = tid >> 5;             \
    const int wm = (wid >> 2) * 64, wn = (wid & 3) * 32;                      \
    const int wmb = wm >> 4, wnb = wn >> 3;                                   \
    const int g = lane >> 2, tg = lane & 3;                                   \
    float acc[4][4][4];                                                       \
    _Pragma("unroll")                                                         \
    for (int i = 0; i < 4; i++)                                               \
        _Pragma("unroll")                                                     \
        for (int j = 0; j < 4; j++)                                           \
            _Pragma("unroll")                                                 \
            for (int q = 0; q < 4; q++) acc[i][j][q] = 0.f;

#define GEMM_EPILOGUE(CPTR, BIASPTR, ALPHA)                                   \
    _Pragma("unroll")                                                         \
    for (int mt = 0; mt < 4; mt++) {                                          \
        int r0 = m0 + wm + mt * 16 + g;                                       \
        _Pragma("unroll")                                                     \
        for (int nt = 0; nt < 4; nt++) {                                      \
            int c = n0 + wn + nt * 8 + 2 * tg;                                \
            float2 bv = *(const float2*)((BIASPTR) + c);                      \
            float2 o0, o1;                                                    \
            o0.x = (ALPHA) * (acc[mt][nt][0] + bv.x);                         \
            o0.y = (ALPHA) * (acc[mt][nt][1] + bv.y);                         \
            o1.x = (ALPHA) * (acc[mt][nt][2] + bv.x);                         \
            o1.y = (ALPHA) * (acc[mt][nt][3] + bv.y);                         \
            *(float2*)((CPTR) + (long)r0 * E_DIM + c) = o0;                   \
            *(float2*)((CPTR) + (long)(r0 + 8) * E_DIM + c) = o1;             \
        }                                                                     \
    }

// ---------------------------------------------------------------------------
// Merged QKV projection: grid (24, 32); seg = blockIdx.x>>3 picks q/k/v.
// ---------------------------------------------------------------------------
__global__ void __launch_bounds__(256) gemm_qkv(
    const float* __restrict__ query, const float* __restrict__ key,
    const float* __restrict__ value, const float* __restrict__ ipw,
    const float* __restrict__ ipb,
    float* __restrict__ Qo, float* __restrict__ Ko, float* __restrict__ Vo)
{
    GEMM_PROLOGUE
    const int m0 = blockIdx.y * 128;
    const int seg = blockIdx.x >> 3;
    const int n0 = (blockIdx.x & 7) * 128;

    const float* A = (seg == 0) ? query : (seg == 1) ? key : value;
    const float* W = ipw + (long)seg * E_DIM * E_DIM;
    const float* bias = ipb + seg * E_DIM;
    float* C = (seg == 0) ? Qo : (seg == 1) ? Ko : Vo;
    const float alpha = (seg == 0) ? 0.125f : 1.0f;

    GEMM_DB_CORE(A, W)
    GEMM_EPILOGUE(C, bias, alpha)
}

// ---------------------------------------------------------------------------
// Output projection
// ---------------------------------------------------------------------------
__global__ void __launch_bounds__(256) gemm_out(
    const float* __restrict__ Ain, const float* __restrict__ W,
    const float* __restrict__ bias, float* __restrict__ C)
{
    GEMM_PROLOGUE
    const int m0 = blockIdx.y * 128, n0 = blockIdx.x * 128;

    GEMM_DB_CORE(Ain, W)
    GEMM_EPILOGUE(C, bias, 1.0f)
}

// ---------------------------------------------------------------------------
// Score kernel (R6 structure + staging swizzle): scores = Q K^T + masks.
// Element (k,m) stored at As[(k&~3) + ((k%4 + m + (k>>3))&3)][m].
// Staging STS: 4-way -> conflict-free. Loads: cc = (tg + g + sb)&3.
// ---------------------------------------------------------------------------
__global__ void __launch_bounds__(256) score_kernel(
    const float* __restrict__ Q, const float* __restrict__ Kx,
    const float* __restrict__ amask, const int* __restrict__ pad,
    float* __restrict__ Sc)
{
    __shared__ uint32_t As[PBK][LDA];
    __shared__ uint32_t Bs[PBK][LDA];
    const int tid = threadIdx.x, lane = tid & 31, wid = tid >> 5;
    const int wm = (wid >> 2) * 64, wn = (wid & 3) * 32;
    const int t0 = blockIdx.y * 128, s0 = blockIdx.x * 128;
    const int z = blockIdx.z;
    const int b = z >> 4, h = z & 15;
    const int g = lane >> 2, tg = lane & 3;
    const float* Qb = Q + (long)b * E_DIM + h * D_DIM;
    const float* Kb = Kx + (long)b * E_DIM + h * D_DIM;

    float acc[4][4][4];
    #pragma unroll
    for (int i = 0; i < 4; i++)
        #pragma unroll
        for (int j = 0; j < 4; j++)
            #pragma unroll
            for (int q = 0; q < 4; q++) acc[i][j][q] = 0.f;

    #pragma unroll
    for (int k0 = 0; k0 < D_DIM; k0 += PBK) {
        #pragma unroll
        for (int p = 0; p < 4; p++) {
            int idx = tid + p * 256;
            int row = idx >> 3, kc = (idx & 7) << 2;
            int sbq = (idx & 7) >> 1;
            int R = (row + sbq) & 3;
            float4 q4 = *(const float4*)(Qb + (long)(t0 + row) * BE + k0 + kc);
            float4 k4 = *(const float4*)(Kb + (long)(s0 + row) * BE + k0 + kc);
            As[kc + ((0 + R) & 3)][row] = f2tf(q4.x);
            As[kc + ((1 + R) & 3)][row] = f2tf(q4.y);
            As[kc + ((2 + R) & 3)][row] = f2tf(q4.z);
            As[kc + ((3 + R) & 3)][row] = f2tf(q4.w);
            Bs[kc + ((0 + R) & 3)][row] = f2tf(k4.x);
            Bs[kc + ((1 + R) & 3)][row] = f2tf(k4.y);
            Bs[kc + ((2 + R) & 3)][row] = f2tf(k4.z);
            Bs[kc + ((3 + R) & 3)][row] = f2tf(k4.w);
        }
        __syncthreads();
        #pragma unroll
        for (int ks = 0; ks < PBK; ks += 8) {
            const int sb = ks >> 3;
            const int cc = (tg + g + sb) & 3;
            uint32_t af[4][4], bf[4][2];
            #pragma unroll
            for (int mt = 0; mt < 4; mt++) {
                int r = wm + mt * 16 + g;
                af[mt][0] = As[ks + cc][r];
                af[mt][1] = As[ks + cc][r + 8];
                af[mt][2] = As[ks + 4 + cc][r];
                af[mt][3] = As[ks + 4 + cc][r + 8];
            }
            #pragma unroll
            for (int nt = 0; nt < 4; nt++) {
                int n = wn + nt * 8 + g;
                bf[nt][0] = Bs[ks + cc][n];
                bf[nt][1] = Bs[ks + 4 + cc][n];
            }
            #pragma unroll
            for (int mt = 0; mt < 4; mt++)
                #pragma unroll
                for (int nt = 0; nt < 4; nt++)
                    mma8(acc[mt][nt], af[mt], bf[nt]);
        }
        __syncthreads();
    }

    float* So = Sc + (long)z * T_DIM * S_DIM;
    #pragma unroll
    for (int mt = 0; mt < 4; mt++) {
        int t = t0 + wm + mt * 16 + g;
        #pragma unroll
        for (int nt = 0; nt < 4; nt++) {
            int s = s0 + wn + nt * 8 + 2 * tg;
            float p0 = pad[b * S_DIM + s]     ? -1e30f : 0.f;
            float p1 = pad[b * S_DIM + s + 1] ? -1e30f : 0.f;
            float2 a0 = *(const float2*)(amask + (long)t * S_DIM + s);
            float2 a1 = *(const float2*)(amask + (long)(t + 8) * S_DIM + s);
            float2 o0, o1;
            o0.x = acc[mt][nt][0] + a0.x + p0;
            o0.y = acc[mt][nt][1] + a0.y + p1;
            o1.x = acc[mt][nt][2] + a1.x + p0;
            o1.y = acc[mt][nt][3] + a1.y + p1;
            *(float2*)(So + (long)t * S_DIM + s) = o0;
            *(float2*)(So + (long)(t + 8) * S_DIM + s) = o1;
        }
    }
}

// ---------------------------------------------------------------------------
// Softmax + head-average (verbatim): block = (b,t), 16 warps = 16 heads.
// ---------------------------------------------------------------------------
#define SA_SMEM_BYTES (H_DIM * S_DIM * 4)   // 65536

__global__ void __launch_bounds__(512) softmax_avg(
    float* __restrict__ P, float* __restrict__ avgw)
{
    extern __shared__ float Ps[];            // [16][1024]
    const int bid = blockIdx.x;
    const int b = bid >> 10, t = bid & 1023;
    const int h = threadIdx.x >> 5, lane = threadIdx.x & 31;

    float4* p = (float4*)(P + (((long)(b * H_DIM + h) * T_DIM) + t) * S_DIM);
    float4 v[8];
    float m = -1e30f;
    #pragma unroll
    for (int i = 0; i < 8; i++) {
        v[i] = p[lane + 32 * i];
        m = fmaxf(m, fmaxf(fmaxf(v[i].x, v[i].y), fmaxf(v[i].z, v[i].w)));
    }
    #pragma unroll
    for (int o = 16; o; o >>= 1) m = fmaxf(m, __shfl_xor_sync(0xffffffffu, m, o));
    float sum = 0.f;
    #pragma unroll
    for (int i = 0; i < 8; i++) {
        v[i].x = __expf(v[i].x - m); v[i].y = __expf(v[i].y - m);
        v[i].z = __expf(v[i].z - m); v[i].w = __expf(v[i].w - m);
        sum += v[i].x + v[i].y + v[i].z + v[i].w;
    }
    #pragma unroll
    for (int o = 16; o; o >>= 1) sum += __shfl_xor_sync(0xffffffffu, sum, o);
    float inv = 1.0f / sum;
    float4* ps = (float4*)(Ps + h * S_DIM);
    #pragma unroll
    for (int i = 0; i < 8; i++) {
        v[i].x *= inv; v[i].y *= inv; v[i].z *= inv; v[i].w *= inv;
        p[lane + 32 * i] = v[i];
        ps[lane + 32 * i] = v[i];
    }
    __syncthreads();

    int s2 = threadIdx.x * 2;
    float a0 = 0.f, a1 = 0.f;
    #pragma unroll
    for (int hh = 0; hh < H_DIM; hh++) {
        float2 pv = *(const float2*)(Ps + hh * S_DIM + s2);
        a0 += pv.x; a1 += pv.y;
    }
    const float inv16 = 1.0f / H_DIM;
    *(float2*)(avgw + ((long)b * T_DIM + t) * S_DIM + s2) =
        make_float2(a0 * inv16, a1 * inv16);
}

// ---------------------------------------------------------------------------
// PV (R6 structure + A-staging swizzle): Ctx[b,h] = P[z] @ V[b,h].
// ---------------------------------------------------------------------------
#define VLDB 72
#define PV_SMEM_BYTES ((2 * PBK * LDA + 2 * PBK * VLDB) * 4)   // 52224

__global__ void __launch_bounds__(256) pv_kernel(
    const float* __restrict__ Sc, const float* __restrict__ V,
    float* __restrict__ Ctx)
{
    extern __shared__ uint32_t dsm[];
    uint32_t* As = dsm;                       // [2*PBK][LDA]
    uint32_t* Bs = dsm + 2 * PBK * LDA;       // [2*PBK][VLDB]
    const int tid = threadIdx.x, lane = tid & 31, wid = tid >> 5;
    const int wm = (wid >> 1) * 32, wn = (wid & 1) * 32;
    const int t0 = blockIdx.x * 128;
    const int z = blockIdx.z;
    const int b = z >> 4, h = z & 15;
    const int g = lane >> 2, tg = lane & 3;
    const float* Pb = Sc + (long)z * T_DIM * S_DIM;
    const float* Vb = V + (long)b * E_DIM + h * D_DIM;

    float acc[2][4][4];
    #pragma unroll
    for (int i = 0; i < 2; i++)
        #pragma unroll
        for (int j = 0; j < 4; j++)
            #pragma unroll
            for (int q = 0; q < 4; q++) acc[i][j][q] = 0.f;

    const int arow = tid >> 3, akc = (tid & 7) << 2;
    const int asbq = (tid & 7) >> 1;          // akc>>3
    const int bs_s = tid >> 4, bs_d = (tid & 15) << 2;

    float4 pa[4], pv[2];
    #pragma unroll
    for (int p = 0; p < 4; p++)
        pa[p] = *(const float4*)(Pb + (long)(t0 + arow + p * 32) * S_DIM + akc);
    #pragma unroll
    for (int p = 0; p < 2; p++)
        pv[p] = *(const float4*)(Vb + (long)(bs_s + p * 16) * BE + bs_d);

#define PV_ASTAGE(BASEOFF)                                                    \
    _Pragma("unroll")                                                         \
    for (int p = 0; p < 4; p++) {                                             \
        int row = arow + p * 32;                                              \
        int R = (row + asbq) & 3;                                             \
        As[((BASEOFF) + akc + ((0 + R) & 3)) * LDA + row] = f2tf(pa[p].x);    \
        As[((BASEOFF) + akc + ((1 + R) & 3)) * LDA + row] = f2tf(pa[p].y);    \
        As[((BASEOFF) + akc + ((2 + R) & 3)) * LDA + row] = f2tf(pa[p].z);    \
        As[((BASEOFF) + akc + ((3 + R) & 3)) * LDA + row] = f2tf(pa[p].w);    \
    }

#define PV_BSTAGE(BASEOFF)                                                    \
    _Pragma("unroll")                                                         \
    for (int p = 0; p < 2; p++) {                                             \
        int s = bs_s + p * 16;                                                \
        Bs[((BASEOFF) + s) * VLDB + bs_d + 0] = f2tf(pv[p].x);                \
        Bs[((BASEOFF) + s) * VLDB + bs_d + 1] = f2tf(pv[p].y);                \
        Bs[((BASEOFF) + s) * VLDB + bs_d + 2] = f2tf(pv[p].z);                \
        Bs[((BASEOFF) + s) * VLDB + bs_d + 3] = f2tf(pv[p].w);                \
    }

    PV_ASTAGE(0)
    PV_BSTAGE(0)

    for (int it = 0; it < S_DIM / PBK; it++) {
        const int cur = (it & 1) * PBK;
        __syncthreads();
        if (it < S_DIM / PBK - 1) {
            int k0 = (it + 1) * PBK;
            #pragma unroll
            for (int p = 0; p < 4; p++)
                pa[p] = *(const float4*)(Pb + (long)(t0 + arow + p * 32) * S_DIM + k0 + akc);
            #pragma unroll
            for (int p = 0; p < 2; p++)
                pv[p] = *(const float4*)(Vb + (long)(k0 + bs_s + p * 16) * BE + bs_d);
        }
        #pragma unroll
        for (int ks = 0; ks < PBK; ks += 8) {
            const int sb = ks >> 3;
            const int cc = (tg + g + sb) & 3;
            uint32_t af[2][4], bf[4][2];
            #pragma unroll
            for (int mt = 0; mt < 2; mt++) {
                int r = wm + mt * 16 + g;
                af[mt][0] = As[(cur + ks + cc) * LDA + r];
                af[mt][1] = As[(cur + ks + cc) * LDA + r + 8];
                af[mt][2] = As[(cur + ks + 4 + cc) * LDA + r];
                af[mt][3] = As[(cur + ks + 4 + cc) * LDA + r + 8];
            }
            #pragma unroll
            for (int nt = 0; nt < 4; nt++) {
                int n = wn + nt * 8 + g;
                bf[nt][0] = Bs[(cur + ks + tg) * VLDB + n];
                bf[nt][1] = Bs[(cur + ks + tg + 4) * VLDB + n];
            }
            #pragma unroll
            for (int mt = 0; mt < 2; mt++)
                #pragma unroll
                for (int nt = 0; nt < 4; nt++)
                    mma8(acc[mt][nt], af[mt], bf[nt]);
        }
        if (it < S_DIM / PBK - 1) {
            const int nxt = ((it + 1) & 1) * PBK;
            PV_ASTAGE(nxt)
            PV_BSTAGE(nxt)
        }
    }

    #pragma unroll
    for (int mt = 0; mt < 2; mt++) {
        int t = t0 + wm + mt * 16 + g;
        #pragma unroll
        for (int nt = 0; nt < 4; nt++) {
            int d = wn + nt * 8 + 2 * tg;
            *(float2*)(Ctx + (long)t * BE + b * E_DIM + h * D_DIM + d) =
                make_float2(acc[mt][nt][0], acc[mt][nt][1]);
            *(float2*)(Ctx + (long)(t + 8) * BE + b * E_DIM + h * D_DIM + d) =
                make_float2(acc[mt][nt][2], acc[mt][nt][3]);
        }
    }
}

// ---------------------------------------------------------------------------
extern "C" void kernel_launch(void* const* d_in, const int* in_sizes, int n_in,
                              void* d_out, int out_size) {
    const float* query = (const float*)d_in[0];
    const float* key   = (const float*)d_in[1];
    const float* value = (const float*)d_in[2];
    const int*   pad   = (const int*)d_in[3];
    const float* amask = (const float*)d_in[4];
    const float* ipw   = (const float*)d_in[5];
    const float* ipb   = (const float*)d_in[6];
    const float* ow    = (const float*)d_in[7];
    const float* ob    = (const float*)d_in[8];

    float* out  = (float*)d_out;
    float* avgw = out + (long)T_DIM * B_DIM * E_DIM;

    float *Qp, *Kp, *Vp, *Cp, *Pp;
    cudaGetSymbolAddress((void**)&Qp, g_Q);
    cudaGetSymbolAddress((void**)&Kp, g_K);
    cudaGetSymbolAddress((void**)&Vp, g_V);
    cudaGetSymbolAddress((void**)&Cp, g_Ctx);
    cudaGetSymbolAddress((void**)&Pp, g_P);

    cudaFuncSetAttribute(gemm_qkv,
        cudaFuncAttributeMaxDynamicSharedMemorySize, GEMM_SMEM_BYTES);
    cudaFuncSetAttribute(gemm_out,
        cudaFuncAttributeMaxDynamicSharedMemorySize, GEMM_SMEM_BYTES);
    cudaFuncSetAttribute(softmax_avg,
        cudaFuncAttributeMaxDynamicSharedMemorySize, SA_SMEM_BYTES);
    cudaFuncSetAttribute(pv_kernel,
        cudaFuncAttributeMaxDynamicSharedMemorySize, PV_SMEM_BYTES);

    gemm_qkv<<<dim3(24, 32), 256, GEMM_SMEM_BYTES>>>(
        query, key, value, ipw, ipb, Qp, Kp, Vp);

    score_kernel<<<dim3(8, 8, 64), 256>>>(Qp, Kp, amask, pad, Pp);

    softmax_avg<<<B_DIM * T_DIM, 512, SA_SMEM_BYTES>>>(Pp, avgw);

    pv_kernel<<<dim3(8, 1, 64), 256, PV_SMEM_BYTES>>>(Pp, Vp, Cp);

    gemm_out<<<dim3(8, 32), 256, GEMM_SMEM_BYTES>>>(Cp, ow, ob, out);
}

// round 12
// speedup vs baseline: 1.3670x; 1.0447x over previous
#include <cuda_runtime.h>
#include <cstdint>

// Problem constants
#define T_DIM 1024
#define B_DIM 4
#define S_DIM 1024
#define E_DIM 1024
#define H_DIM 16
#define D_DIM 64
#define TB (T_DIM * B_DIM)
#define BE (B_DIM * E_DIM)

// Scratch (device globals — no allocation allowed)
__device__ float g_Q[TB * E_DIM];
__device__ float g_K[TB * E_DIM];
__device__ float g_V[TB * E_DIM];
__device__ float g_Ctx[TB * E_DIM];
__device__ float g_P[(long)B_DIM * H_DIM * T_DIM * S_DIM];   // scores -> probs (256 MB)

// ---------------------------------------------------------------------------
// tf32 helpers
// ---------------------------------------------------------------------------
__device__ __forceinline__ uint32_t f2tf(float x) {
    uint32_t r;
    asm("cvt.rna.tf32.f32 %0, %1;" : "=r"(r) : "f"(x));
    return r;
}

__device__ __forceinline__ void mma8(float* d, const uint32_t* a, const uint32_t* b) {
    asm volatile(
        "mma.sync.aligned.m16n8k8.row.col.f32.tf32.tf32.f32 "
        "{%0,%1,%2,%3}, {%4,%5,%6,%7}, {%8,%9}, {%0,%1,%2,%3};\n"
        : "+f"(d[0]), "+f"(d[1]), "+f"(d[2]), "+f"(d[3])
        : "r"(a[0]), "r"(a[1]), "r"(a[2]), "r"(a[3]), "r"(b[0]), "r"(b[1]));
}

#define PBK 32
#define LDA 132

// ---------------------------------------------------------------------------
// Fragment-interleaved layout + staging rotation (validated R9/R11):
// A word = ((sb*8 + m/16)*32 + (m%8)*4 + ((k%4 + m + sb)&3))*4
//          + ((k%8)>=4)*2 + ((m%16)>=8)
// B word = ((sb*16 + n/8)*32 + (n%8)*4 + ((k%4 + n + sb)&3))*2 + ((k%8)>=4)
// Mainloop: a-frag = 1 LDS.128, b-frag = 1 LDS.64 at
//   sw = g*4 + ((tg + g + sb)&3).
// ---------------------------------------------------------------------------
#define GEMM_SMEM_WORDS 16384
#define GEMM_SMEM_BYTES (GEMM_SMEM_WORDS * 4)   // 65536

#define GEMM_STAGE(DSTA, DSTB, PA, PW)                                        \
    _Pragma("unroll")                                                         \
    for (int p = 0; p < 4; p++) {                                             \
        int row = lrow + p * 32;                                              \
        int mbq = row >> 4, fragm = ((row & 15) >= 8) ? 1 : 0;                \
        int nb8 = row >> 3;                                                   \
        int laneb = (row & 7) * 4;                                            \
        int R = (row + sbq) & 3;                                              \
        uint32_t* aw = (DSTA) + ((sbq * 8 + mbq) * 32 + laneb) * 4 + fragk2 + fragm; \
        uint32_t* bw = (DSTB) + ((sbq * 16 + nb8) * 32 + laneb) * 2 + fragb;  \
        aw[4 * ((0 + R) & 3)] = f2tf((PA)[p].x);                              \
        aw[4 * ((1 + R) & 3)] = f2tf((PA)[p].y);                              \
        aw[4 * ((2 + R) & 3)] = f2tf((PA)[p].z);                              \
        aw[4 * ((3 + R) & 3)] = f2tf((PA)[p].w);                              \
        bw[2 * ((0 + R) & 3)] = f2tf((PW)[p].x);                              \
        bw[2 * ((1 + R) & 3)] = f2tf((PW)[p].y);                              \
        bw[2 * ((2 + R) & 3)] = f2tf((PW)[p].z);                              \
        bw[2 * ((3 + R) & 3)] = f2tf((PW)[p].w);                              \
    }

#define GEMM_DB_CORE(APTR, WPTR)                                              \
    const int lrow = tid >> 3, lkc = (tid & 7) << 2;                          \
    const int sbq = lkc >> 3;                                                 \
    const int fragk2 = ((lkc & 7) >= 4) ? 2 : 0;                              \
    const int fragb  = ((lkc & 7) >= 4) ? 1 : 0;                              \
    float4 pa[4], pw[4];                                                      \
    _Pragma("unroll")                                                         \
    for (int p = 0; p < 4; p++) {                                             \
        int row = lrow + p * 32;                                              \
        pa[p] = *(const float4*)((APTR) + (long)(m0 + row) * E_DIM + lkc);    \
        pw[p] = *(const float4*)((WPTR) + (long)(n0 + row) * E_DIM + lkc);    \
    }                                                                         \
    GEMM_STAGE(As, Bs, pa, pw)                                                \
    for (int it = 0; it < E_DIM / PBK; it++) {                                \
        const int cur = (it & 1) * 4096;                                      \
        __syncthreads();                                                      \
        if (it < E_DIM / PBK - 1) {                                           \
            int k0 = (it + 1) * PBK;                                          \
            _Pragma("unroll")                                                 \
            for (int p = 0; p < 4; p++) {                                     \
                int row = lrow + p * 32;                                      \
                pa[p] = *(const float4*)((APTR) + (long)(m0 + row) * E_DIM + k0 + lkc); \
                pw[p] = *(const float4*)((WPTR) + (long)(n0 + row) * E_DIM + k0 + lkc); \
            }                                                                 \
        }                                                                     \
        const uint32_t* Acur = As + cur;                                      \
        const uint32_t* Bcur = Bs + cur;                                      \
        _Pragma("unroll")                                                     \
        for (int sb = 0; sb < 4; sb++) {                                      \
            const int sw = (g << 2) + ((tg + g + sb) & 3);                    \
            uint4 af[4];                                                      \
            uint2 bf[4];                                                      \
            _Pragma("unroll")                                                 \
            for (int mt = 0; mt < 4; mt++)                                    \
                af[mt] = *(const uint4*)(Acur + ((sb * 8 + wmb + mt) * 32 + sw) * 4); \
            _Pragma("unroll")                                                 \
            for (int nt = 0; nt < 4; nt++)                                    \
                bf[nt] = *(const uint2*)(Bcur + ((sb * 16 + wnb + nt) * 32 + sw) * 2); \
            _Pragma("unroll")                                                 \
            for (int mt = 0; mt < 4; mt++)                                    \
                _Pragma("unroll")                                             \
                for (int nt = 0; nt < 4; nt++)                                \
                    mma8(acc[mt][nt], (const uint32_t*)&af[mt], (const uint32_t*)&bf[nt]); \
        }                                                                     \
        if (it < E_DIM / PBK - 1) {                                           \
            const int nxt = ((it + 1) & 1) * 4096;                            \
            GEMM_STAGE(As + nxt, Bs + nxt, pa, pw)                            \
        }                                                                     \
    }

#define GEMM_PROLOGUE                                                         \
    extern __shared__ uint32_t dsm[];                                         \
    uint32_t* As = dsm;                                                       \
    uint32_t* Bs = dsm + 8192;                                                \
    const int tid = threadIdx.x, lane = tid & 31, wid = tid >> 5;             \
    const int wm = (wid >> 2) * 64, wn = (wid & 3) * 32;                      \
    const int wmb = wm >> 4, wnb = wn >> 3;                                   \
    const int g = lane >> 2, tg = lane & 3;                                   \
    float acc[4][4][4];                                                       \
    _Pragma("unroll")                                                         \
    for (int i = 0; i < 4; i++)                                               \
        _Pragma("unroll")                                                     \
        for (int j = 0; j < 4; j++)                                           \
            _Pragma("unroll")                                                 \
            for (int q = 0; q < 4; q++) acc[i][j][q] = 0.f;

#define GEMM_EPILOGUE(CPTR, BIASPTR, ALPHA)                                   \
    _Pragma("unroll")                                                         \
    for (int mt = 0; mt < 4; mt++) {                                          \
        int r0 = m0 + wm + mt * 16 + g;                                       \
        _Pragma("unroll")                                                     \
        for (int nt = 0; nt < 4; nt++) {                                      \
            int c = n0 + wn + nt * 8 + 2 * tg;                                \
            float2 bv = *(const float2*)((BIASPTR) + c);                      \
            float2 o0, o1;                                                    \
            o0.x = (ALPHA) * (acc[mt][nt][0] + bv.x);                         \
            o0.y = (ALPHA) * (acc[mt][nt][1] + bv.y);                         \
            o1.x = (ALPHA) * (acc[mt][nt][2] + bv.x);                         \
            o1.y = (ALPHA) * (acc[mt][nt][3] + bv.y);                         \
            *(float2*)((CPTR) + (long)r0 * E_DIM + c) = o0;                   \
            *(float2*)((CPTR) + (long)(r0 + 8) * E_DIM + c) = o1;             \
        }                                                                     \
    }

// ---------------------------------------------------------------------------
// Merged QKV projection: grid (24, 32); seg = blockIdx.x>>3 picks q/k/v.
// ---------------------------------------------------------------------------
__global__ void __launch_bounds__(256) gemm_qkv(
    const float* __restrict__ query, const float* __restrict__ key,
    const float* __restrict__ value, const float* __restrict__ ipw,
    const float* __restrict__ ipb,
    float* __restrict__ Qo, float* __restrict__ Ko, float* __restrict__ Vo)
{
    GEMM_PROLOGUE
    const int m0 = blockIdx.y * 128;
    const int seg = blockIdx.x >> 3;
    const int n0 = (blockIdx.x & 7) * 128;

    const float* A = (seg == 0) ? query : (seg == 1) ? key : value;
    const float* W = ipw + (long)seg * E_DIM * E_DIM;
    const float* bias = ipb + seg * E_DIM;
    float* C = (seg == 0) ? Qo : (seg == 1) ? Ko : Vo;
    const float alpha = (seg == 0) ? 0.125f : 1.0f;

    GEMM_DB_CORE(A, W)
    GEMM_EPILOGUE(C, bias, alpha)
}

// ---------------------------------------------------------------------------
// Output projection
// ---------------------------------------------------------------------------
__global__ void __launch_bounds__(256) gemm_out(
    const float* __restrict__ Ain, const float* __restrict__ W,
    const float* __restrict__ bias, float* __restrict__ C)
{
    GEMM_PROLOGUE
    const int m0 = blockIdx.y * 128, n0 = blockIdx.x * 128;

    GEMM_DB_CORE(Ain, W)
    GEMM_EPILOGUE(C, bias, 1.0f)
}

// ---------------------------------------------------------------------------
// Score kernel — frag-interleaved + rotation (same layout as GEMM core).
// scores[z][T,S] = Q K^T + attn_mask + pad. K=64 staged once, 1 sync.
// A: 8 slabs x 8 mb (8192 w) | B: 8 slabs x 16 nb8 (8192 w) = 64KB.
// ---------------------------------------------------------------------------
#define SCORE_SMEM_BYTES (16384 * 4)

__global__ void __launch_bounds__(256) score_kernel(
    const float* __restrict__ Q, const float* __restrict__ Kx,
    const float* __restrict__ amask, const int* __restrict__ pad,
    float* __restrict__ Sc)
{
    extern __shared__ uint32_t dsm[];
    uint32_t* As = dsm;                 // 8192 words
    uint32_t* Bs = dsm + 8192;          // 8192 words
    const int tid = threadIdx.x, lane = tid & 31, wid = tid >> 5;
    const int wm = (wid >> 2) * 64, wn = (wid & 3) * 32;
    const int wmb = wm >> 4, wnb = wn >> 3;
    const int t0 = blockIdx.y * 128, s0 = blockIdx.x * 128;
    const int z = blockIdx.z;
    const int b = z >> 4, h = z & 15;
    const int g = lane >> 2, tg = lane & 3;
    const float* Qb = Q + (long)b * E_DIM + h * D_DIM;
    const float* Kb = Kx + (long)b * E_DIM + h * D_DIM;

    float acc[4][4][4];
    #pragma unroll
    for (int i = 0; i < 4; i++)
        #pragma unroll
        for (int j = 0; j < 4; j++)
            #pragma unroll
            for (int q = 0; q < 4; q++) acc[i][j][q] = 0.f;

    // stage all K=64 in frag+rot layout
    {
        const int srow = tid >> 3;            // 0..31 (+pr*32)
        const int skc = (tid & 7) << 2;       // 0,4,...,28 (+pk*32)
        #pragma unroll
        for (int pr = 0; pr < 4; pr++) {
            int row = srow + pr * 32;
            int mbq = row >> 4, fragm = ((row & 15) >= 8) ? 1 : 0;
            int nb8 = row >> 3;
            int laneb = (row & 7) * 4;
            #pragma unroll
            for (int pk = 0; pk < 2; pk++) {
                int kc = skc + pk * 32;
                int sb = kc >> 3;
                int fragk2 = ((kc & 7) >= 4) ? 2 : 0;
                int fb = ((kc & 7) >= 4) ? 1 : 0;
                int R = (row + sb) & 3;
                float4 q4 = *(const float4*)(Qb + (long)(t0 + row) * BE + kc);
                float4 k4 = *(const float4*)(Kb + (long)(s0 + row) * BE + kc);
                uint32_t* aw = As + ((sb * 8 + mbq) * 32 + laneb) * 4 + fragk2 + fragm;
                uint32_t* bw = Bs + ((sb * 16 + nb8) * 32 + laneb) * 2 + fb;
                aw[4 * ((0 + R) & 3)] = f2tf(q4.x);
                aw[4 * ((1 + R) & 3)] = f2tf(q4.y);
                aw[4 * ((2 + R) & 3)] = f2tf(q4.z);
                aw[4 * ((3 + R) & 3)] = f2tf(q4.w);
                bw[2 * ((0 + R) & 3)] = f2tf(k4.x);
                bw[2 * ((1 + R) & 3)] = f2tf(k4.y);
                bw[2 * ((2 + R) & 3)] = f2tf(k4.z);
                bw[2 * ((3 + R) & 3)] = f2tf(k4.w);
            }
        }
    }
    __syncthreads();

    #pragma unroll
    for (int sb = 0; sb < 8; sb++) {
        const int sw = (g << 2) + ((tg + g + sb) & 3);
        uint4 af[4];
        uint2 bf[4];
        #pragma unroll
        for (int mt = 0; mt < 4; mt++)
            af[mt] = *(const uint4*)(As + ((sb * 8 + wmb + mt) * 32 + sw) * 4);
        #pragma unroll
        for (int nt = 0; nt < 4; nt++)
            bf[nt] = *(const uint2*)(Bs + ((sb * 16 + wnb + nt) * 32 + sw) * 2);
        #pragma unroll
        for (int mt = 0; mt < 4; mt++)
            #pragma unroll
            for (int nt = 0; nt < 4; nt++)
                mma8(acc[mt][nt], (const uint32_t*)&af[mt], (const uint32_t*)&bf[nt]);
    }

    float* So = Sc + (long)z * T_DIM * S_DIM;
    #pragma unroll
    for (int mt = 0; mt < 4; mt++) {
        int t = t0 + wm + mt * 16 + g;
        #pragma unroll
        for (int nt = 0; nt < 4; nt++) {
            int s = s0 + wn + nt * 8 + 2 * tg;
            float p0 = pad[b * S_DIM + s]     ? -1e30f : 0.f;
            float p1 = pad[b * S_DIM + s + 1] ? -1e30f : 0.f;
            float2 a0 = *(const float2*)(amask + (long)t * S_DIM + s);
            float2 a1 = *(const float2*)(amask + (long)(t + 8) * S_DIM + s);
            float2 o0, o1;
            o0.x = acc[mt][nt][0] + a0.x + p0;
            o0.y = acc[mt][nt][1] + a0.y + p1;
            o1.x = acc[mt][nt][2] + a1.x + p0;
            o1.y = acc[mt][nt][3] + a1.y + p1;
            *(float2*)(So + (long)t * S_DIM + s) = o0;
            *(float2*)(So + (long)(t + 8) * S_DIM + s) = o1;
        }
    }
}

// ---------------------------------------------------------------------------
// Softmax + head-average (verbatim): block = (b,t), 16 warps = 16 heads.
// ---------------------------------------------------------------------------
#define SA_SMEM_BYTES (H_DIM * S_DIM * 4)   // 65536

__global__ void __launch_bounds__(512) softmax_avg(
    float* __restrict__ P, float* __restrict__ avgw)
{
    extern __shared__ float Ps[];            // [16][1024]
    const int bid = blockIdx.x;
    const int b = bid >> 10, t = bid & 1023;
    const int h = threadIdx.x >> 5, lane = threadIdx.x & 31;

    float4* p = (float4*)(P + (((long)(b * H_DIM + h) * T_DIM) + t) * S_DIM);
    float4 v[8];
    float m = -1e30f;
    #pragma unroll
    for (int i = 0; i < 8; i++) {
        v[i] = p[lane + 32 * i];
        m = fmaxf(m, fmaxf(fmaxf(v[i].x, v[i].y), fmaxf(v[i].z, v[i].w)));
    }
    #pragma unroll
    for (int o = 16; o; o >>= 1) m = fmaxf(m, __shfl_xor_sync(0xffffffffu, m, o));
    float sum = 0.f;
    #pragma unroll
    for (int i = 0; i < 8; i++) {
        v[i].x = __expf(v[i].x - m); v[i].y = __expf(v[i].y - m);
        v[i].z = __expf(v[i].z - m); v[i].w = __expf(v[i].w - m);
        sum += v[i].x + v[i].y + v[i].z + v[i].w;
    }
    #pragma unroll
    for (int o = 16; o; o >>= 1) sum += __shfl_xor_sync(0xffffffffu, sum, o);
    float inv = 1.0f / sum;
    float4* ps = (float4*)(Ps + h * S_DIM);
    #pragma unroll
    for (int i = 0; i < 8; i++) {
        v[i].x *= inv; v[i].y *= inv; v[i].z *= inv; v[i].w *= inv;
        p[lane + 32 * i] = v[i];
        ps[lane + 32 * i] = v[i];
    }
    __syncthreads();

    int s2 = threadIdx.x * 2;
    float a0 = 0.f, a1 = 0.f;
    #pragma unroll
    for (int hh = 0; hh < H_DIM; hh++) {
        float2 pv = *(const float2*)(Ps + hh * S_DIM + s2);
        a0 += pv.x; a1 += pv.y;
    }
    const float inv16 = 1.0f / H_DIM;
    *(float2*)(avgw + ((long)b * T_DIM + t) * S_DIM + s2) =
        make_float2(a0 * inv16, a1 * inv16);
}

// ---------------------------------------------------------------------------
// PV (R11 verbatim — simple layout + A-staging swizzle)
// ---------------------------------------------------------------------------
#define VLDB 72
#define PV_SMEM_BYTES ((2 * PBK * LDA + 2 * PBK * VLDB) * 4)   // 52224

__global__ void __launch_bounds__(256) pv_kernel(
    const float* __restrict__ Sc, const float* __restrict__ V,
    float* __restrict__ Ctx)
{
    extern __shared__ uint32_t dsm[];
    uint32_t* As = dsm;                       // [2*PBK][LDA]
    uint32_t* Bs = dsm + 2 * PBK * LDA;       // [2*PBK][VLDB]
    const int tid = threadIdx.x, lane = tid & 31, wid = tid >> 5;
    const int wm = (wid >> 1) * 32, wn = (wid & 1) * 32;
    const int t0 = blockIdx.x * 128;
    const int z = blockIdx.z;
    const int b = z >> 4, h = z & 15;
    const int g = lane >> 2, tg = lane & 3;
    const float* Pb = Sc + (long)z * T_DIM * S_DIM;
    const float* Vb = V + (long)b * E_DIM + h * D_DIM;

    float acc[2][4][4];
    #pragma unroll
    for (int i = 0; i < 2; i++)
        #pragma unroll
        for (int j = 0; j < 4; j++)
            #pragma unroll
            for (int q = 0; q < 4; q++) acc[i][j][q] = 0.f;

    const int arow = tid >> 3, akc = (tid & 7) << 2;
    const int asbq = (tid & 7) >> 1;          // akc>>3
    const int bs_s = tid >> 4, bs_d = (tid & 15) << 2;

    float4 pa[4], pv[2];
    #pragma unroll
    for (int p = 0; p < 4; p++)
        pa[p] = *(const float4*)(Pb + (long)(t0 + arow + p * 32) * S_DIM + akc);
    #pragma unroll
    for (int p = 0; p < 2; p++)
        pv[p] = *(const float4*)(Vb + (long)(bs_s + p * 16) * BE + bs_d);

#define PV_ASTAGE(BASEOFF)                                                    \
    _Pragma("unroll")                                                         \
    for (int p = 0; p < 4; p++) {                                             \
        int row = arow + p * 32;                                              \
        int R = (row + asbq) & 3;                                             \
        As[((BASEOFF) + akc + ((0 + R) & 3)) * LDA + row] = f2tf(pa[p].x);    \
        As[((BASEOFF) + akc + ((1 + R) & 3)) * LDA + row] = f2tf(pa[p].y);    \
        As[((BASEOFF) + akc + ((2 + R) & 3)) * LDA + row] = f2tf(pa[p].z);    \
        As[((BASEOFF) + akc + ((3 + R) & 3)) * LDA + row] = f2tf(pa[p].w);    \
    }

#define PV_BSTAGE(BASEOFF)                                                    \
    _Pragma("unroll")                                                         \
    for (int p = 0; p < 2; p++) {                                             \
        int s = bs_s + p * 16;                                                \
        Bs[((BASEOFF) + s) * VLDB + bs_d + 0] = f2tf(pv[p].x);                \
        Bs[((BASEOFF) + s) * VLDB + bs_d + 1] = f2tf(pv[p].y);                \
        Bs[((BASEOFF) + s) * VLDB + bs_d + 2] = f2tf(pv[p].z);                \
        Bs[((BASEOFF) + s) * VLDB + bs_d + 3] = f2tf(pv[p].w);                \
    }

    PV_ASTAGE(0)
    PV_BSTAGE(0)

    for (int it = 0; it < S_DIM / PBK; it++) {
        const int cur = (it & 1) * PBK;
        __syncthreads();
        if (it < S_DIM / PBK - 1) {
            int k0 = (it + 1) * PBK;
            #pragma unroll
            for (int p = 0; p < 4; p++)
                pa[p] = *(const float4*)(Pb + (long)(t0 + arow + p * 32) * S_DIM + k0 + akc);
            #pragma unroll
            for (int p = 0; p < 2; p++)
                pv[p] = *(const float4*)(Vb + (long)(k0 + bs_s + p * 16) * BE + bs_d);
        }
        #pragma unroll
        for (int ks = 0; ks < PBK; ks += 8) {
            const int sb = ks >> 3;
            const int cc = (tg + g + sb) & 3;
            uint32_t af[2][4], bf[4][2];
            #pragma unroll
            for (int mt = 0; mt < 2; mt++) {
                int r = wm + mt * 16 + g;
                af[mt][0] = As[(cur + ks + cc) * LDA + r];
                af[mt][1] = As[(cur + ks + cc) * LDA + r + 8];
                af[mt][2] = As[(cur + ks + 4 + cc) * LDA + r];
                af[mt][3] = As[(cur + ks + 4 + cc) * LDA + r + 8];
            }
            #pragma unroll
            for (int nt = 0; nt < 4; nt++) {
                int n = wn + nt * 8 + g;
                bf[nt][0] = Bs[(cur + ks + tg) * VLDB + n];
                bf[nt][1] = Bs[(cur + ks + tg + 4) * VLDB + n];
            }
            #pragma unroll
            for (int mt = 0; mt < 2; mt++)
                #pragma unroll
                for (int nt = 0; nt < 4; nt++)
                    mma8(acc[mt][nt], af[mt], bf[nt]);
        }
        if (it < S_DIM / PBK - 1) {
            const int nxt = ((it + 1) & 1) * PBK;
            PV_ASTAGE(nxt)
            PV_BSTAGE(nxt)
        }
    }

    #pragma unroll
    for (int mt = 0; mt < 2; mt++) {
        int t = t0 + wm + mt * 16 + g;
        #pragma unroll
        for (int nt = 0; nt < 4; nt++) {
            int d = wn + nt * 8 + 2 * tg;
            *(float2*)(Ctx + (long)t * BE + b * E_DIM + h * D_DIM + d) =
                make_float2(acc[mt][nt][0], acc[mt][nt][1]);
            *(float2*)(Ctx + (long)(t + 8) * BE + b * E_DIM + h * D_DIM + d) =
                make_float2(acc[mt][nt][2], acc[mt][nt][3]);
        }
    }
}

// ---------------------------------------------------------------------------
extern "C" void kernel_launch(void* const* d_in, const int* in_sizes, int n_in,
                              void* d_out, int out_size) {
    const float* query = (const float*)d_in[0];
    const float* key   = (const float*)d_in[1];
    const float* value = (const float*)d_in[2];
    const int*   pad   = (const int*)d_in[3];
    const float* amask = (const float*)d_in[4];
    const float* ipw   = (const float*)d_in[5];
    const float* ipb   = (const float*)d_in[6];
    const float* ow    = (const float*)d_in[7];
    const float* ob    = (const float*)d_in[8];

    float* out  = (float*)d_out;
    float* avgw = out + (long)T_DIM * B_DIM * E_DIM;

    float *Qp, *Kp, *Vp, *Cp, *Pp;
    cudaGetSymbolAddress((void**)&Qp, g_Q);
    cudaGetSymbolAddress((void**)&Kp, g_K);
    cudaGetSymbolAddress((void**)&Vp, g_V);
    cudaGetSymbolAddress((void**)&Cp, g_Ctx);
    cudaGetSymbolAddress((void**)&Pp, g_P);

    cudaFuncSetAttribute(gemm_qkv,
        cudaFuncAttributeMaxDynamicSharedMemorySize, GEMM_SMEM_BYTES);
    cudaFuncSetAttribute(gemm_out,
        cudaFuncAttributeMaxDynamicSharedMemorySize, GEMM_SMEM_BYTES);
    cudaFuncSetAttribute(score_kernel,
        cudaFuncAttributeMaxDynamicSharedMemorySize, SCORE_SMEM_BYTES);
    cudaFuncSetAttribute(softmax_avg,
        cudaFuncAttributeMaxDynamicSharedMemorySize, SA_SMEM_BYTES);
    cudaFuncSetAttribute(pv_kernel,
        cudaFuncAttributeMaxDynamicSharedMemorySize, PV_SMEM_BYTES);

    gemm_qkv<<<dim3(24, 32), 256, GEMM_SMEM_BYTES>>>(
        query, key, value, ipw, ipb, Qp, Kp, Vp);

    score_kernel<<<dim3(8, 8, 64), 256, SCORE_SMEM_BYTES>>>(
        Qp, Kp, amask, pad, Pp);

    softmax_avg<<<B_DIM * T_DIM, 512, SA_SMEM_BYTES>>>(Pp, avgw);

    pv_kernel<<<dim3(8, 1, 64), 256, PV_SMEM_BYTES>>>(Pp, Vp, Cp);

    gemm_out<<<dim3(8, 32), 256, GEMM_SMEM_BYTES>>>(Cp, ow, ob, out);
}

// round 13
// speedup vs baseline: 1.3751x; 1.0059x over previous
#include <cuda_runtime.h>
#include <cstdint>

// Problem constants
#define T_DIM 1024
#define B_DIM 4
#define S_DIM 1024
#define E_DIM 1024
#define H_DIM 16
#define D_DIM 64
#define TB (T_DIM * B_DIM)
#define BE (B_DIM * E_DIM)

// Scratch (device globals — no allocation allowed)
__device__ float g_Q[TB * E_DIM];
__device__ float g_K[TB * E_DIM];
__device__ float g_V[TB * E_DIM];
__device__ float g_Ctx[TB * E_DIM];
__device__ float g_P[(long)B_DIM * H_DIM * T_DIM * S_DIM];   // scores -> probs (256 MB)

// ---------------------------------------------------------------------------
// tf32 helpers
// ---------------------------------------------------------------------------
__device__ __forceinline__ uint32_t f2tf(float x) {
    uint32_t r;
    asm("cvt.rna.tf32.f32 %0, %1;" : "=r"(r) : "f"(x));
    return r;
}

__device__ __forceinline__ void mma8(float* d, const uint32_t* a, const uint32_t* b) {
    asm volatile(
        "mma.sync.aligned.m16n8k8.row.col.f32.tf32.tf32.f32 "
        "{%0,%1,%2,%3}, {%4,%5,%6,%7}, {%8,%9}, {%0,%1,%2,%3};\n"
        : "+f"(d[0]), "+f"(d[1]), "+f"(d[2]), "+f"(d[3])
        : "r"(a[0]), "r"(a[1]), "r"(a[2]), "r"(a[3]), "r"(b[0]), "r"(b[1]));
}

#define PBK 32
#define LDA 132

// ---------------------------------------------------------------------------
// Fragment-interleaved layout + staging rotation (validated R9/R11/R12):
// A word = ((sb*8 + m/16)*32 + (m%8)*4 + ((k%4 + m + sb)&3))*4
//          + ((k%8)>=4)*2 + ((m%16)>=8)
// B word = ((sb*16 + n/8)*32 + (n%8)*4 + ((k%4 + n + sb)&3))*2 + ((k%8)>=4)
// Mainloop: a-frag = 1 LDS.128, b-frag = 1 LDS.64 at
//   sw = g*4 + ((tg + g + sb)&3).
// ---------------------------------------------------------------------------
#define GEMM_SMEM_WORDS 16384
#define GEMM_SMEM_BYTES (GEMM_SMEM_WORDS * 4)   // 65536

#define GEMM_STAGE(DSTA, DSTB, PA, PW)                                        \
    _Pragma("unroll")                                                         \
    for (int p = 0; p < 4; p++) {                                             \
        int row = lrow + p * 32;                                              \
        int mbq = row >> 4, fragm = ((row & 15) >= 8) ? 1 : 0;                \
        int nb8 = row >> 3;                                                   \
        int laneb = (row & 7) * 4;                                            \
        int R = (row + sbq) & 3;                                              \
        uint32_t* aw = (DSTA) + ((sbq * 8 + mbq) * 32 + laneb) * 4 + fragk2 + fragm; \
        uint32_t* bw = (DSTB) + ((sbq * 16 + nb8) * 32 + laneb) * 2 + fragb;  \
        aw[4 * ((0 + R) & 3)] = f2tf((PA)[p].x);                              \
        aw[4 * ((1 + R) & 3)] = f2tf((PA)[p].y);                              \
        aw[4 * ((2 + R) & 3)] = f2tf((PA)[p].z);                              \
        aw[4 * ((3 + R) & 3)] = f2tf((PA)[p].w);                              \
        bw[2 * ((0 + R) & 3)] = f2tf((PW)[p].x);                              \
        bw[2 * ((1 + R) & 3)] = f2tf((PW)[p].y);                              \
        bw[2 * ((2 + R) & 3)] = f2tf((PW)[p].z);                              \
        bw[2 * ((3 + R) & 3)] = f2tf((PW)[p].w);                              \
    }

#define GEMM_DB_CORE(APTR, WPTR)                                              \
    const int lrow = tid >> 3, lkc = (tid & 7) << 2;                          \
    const int sbq = lkc >> 3;                                                 \
    const int fragk2 = ((lkc & 7) >= 4) ? 2 : 0;                              \
    const int fragb  = ((lkc & 7) >= 4) ? 1 : 0;                              \
    float4 pa[4], pw[4];                                                      \
    _Pragma("unroll")                                                         \
    for (int p = 0; p < 4; p++) {                                             \
        int row = lrow + p * 32;                                              \
        pa[p] = *(const float4*)((APTR) + (long)(m0 + row) * E_DIM + lkc);    \
        pw[p] = *(const float4*)((WPTR) + (long)(n0 + row) * E_DIM + lkc);    \
    }                                                                         \
    GEMM_STAGE(As, Bs, pa, pw)                                                \
    for (int it = 0; it < E_DIM / PBK; it++) {                                \
        const int cur = (it & 1) * 4096;                                      \
        __syncthreads();                                                      \
        if (it < E_DIM / PBK - 1) {                                           \
            int k0 = (it + 1) * PBK;                                          \
            _Pragma("unroll")                                                 \
            for (int p = 0; p < 4; p++) {                                     \
                int row = lrow + p * 32;                                      \
                pa[p] = *(const float4*)((APTR) + (long)(m0 + row) * E_DIM + k0 + lkc); \
                pw[p] = *(const float4*)((WPTR) + (long)(n0 + row) * E_DIM + k0 + lkc); \
            }                                                                 \
        }                                                                     \
        const uint32_t* Acur = As + cur;                                      \
        const uint32_t* Bcur = Bs + cur;                                      \
        _Pragma("unroll")                                                     \
        for (int sb = 0; sb < 4; sb++) {                                      \
            const int sw = (g << 2) + ((tg + g + sb) & 3);                    \
            uint4 af[4];                                                      \
            uint2 bf[4];                                                      \
            _Pragma("unroll")                                                 \
            for (int mt = 0; mt < 4; mt++)                                    \
                af[mt] = *(const uint4*)(Acur + ((sb * 8 + wmb + mt) * 32 + sw) * 4); \
            _Pragma("unroll")                                                 \
            for (int nt = 0; nt < 4; nt++)                                    \
                bf[nt] = *(const uint2*)(Bcur + ((sb * 16 + wnb + nt) * 32 + sw) * 2); \
            _Pragma("unroll")                                                 \
            for (int mt = 0; mt < 4; mt++)                                    \
                _Pragma("unroll")                                             \
                for (int nt = 0; nt < 4; nt++)                                \
                    mma8(acc[mt][nt], (const uint32_t*)&af[mt], (const uint32_t*)&bf[nt]); \
        }                                                                     \
        if (it < E_DIM / PBK - 1) {                                           \
            const int nxt = ((it + 1) & 1) * 4096;                            \
            GEMM_STAGE(As + nxt, Bs + nxt, pa, pw)                            \
        }                                                                     \
    }

#define GEMM_PROLOGUE                                                         \
    extern __shared__ uint32_t dsm[];                                         \
    uint32_t* As = dsm;                                                       \
    uint32_t* Bs = dsm + 8192;                                                \
    const int tid = threadIdx.x, lane = tid & 31, wid = tid >> 5;             \
    const int wm = (wid >> 2) * 64, wn = (wid & 3) * 32;                      \
    const int wmb = wm >> 4, wnb = wn >> 3;                                   \
    const int g = lane >> 2, tg = lane & 3;                                   \
    float acc[4][4][4];                                                       \
    _Pragma("unroll")                                                         \
    for (int i = 0; i < 4; i++)                                               \
        _Pragma("unroll")                                                     \
        for (int j = 0; j < 4; j++)                                           \
            _Pragma("unroll")                                                 \
            for (int q = 0; q < 4; q++) acc[i][j][q] = 0.f;

#define GEMM_EPILOGUE(CPTR, BIASPTR, ALPHA)                                   \
    _Pragma("unroll")                                                         \
    for (int mt = 0; mt < 4; mt++) {                                          \
        int r0 = m0 + wm + mt * 16 + g;                                       \
        _Pragma("unroll")                                                     \
        for (int nt = 0; nt < 4; nt++) {                                      \
            int c = n0 + wn + nt * 8 + 2 * tg;                                \
            float2 bv = *(const float2*)((BIASPTR) + c);                      \
            float2 o0, o1;                                                    \
            o0.x = (ALPHA) * (acc[mt][nt][0] + bv.x);                         \
            o0.y = (ALPHA) * (acc[mt][nt][1] + bv.y);                         \
            o1.x = (ALPHA) * (acc[mt][nt][2] + bv.x);                         \
            o1.y = (ALPHA) * (acc[mt][nt][3] + bv.y);                         \
            *(float2*)((CPTR) + (long)r0 * E_DIM + c) = o0;                   \
            *(float2*)((CPTR) + (long)(r0 + 8) * E_DIM + c) = o1;             \
        }                                                                     \
    }

// ---------------------------------------------------------------------------
// Merged QKV projection: grid (24, 32); seg = blockIdx.x>>3 picks q/k/v.
// ---------------------------------------------------------------------------
__global__ void __launch_bounds__(256) gemm_qkv(
    const float* __restrict__ query, const float* __restrict__ key,
    const float* __restrict__ value, const float* __restrict__ ipw,
    const float* __restrict__ ipb,
    float* __restrict__ Qo, float* __restrict__ Ko, float* __restrict__ Vo)
{
    GEMM_PROLOGUE
    const int m0 = blockIdx.y * 128;
    const int seg = blockIdx.x >> 3;
    const int n0 = (blockIdx.x & 7) * 128;

    const float* A = (seg == 0) ? query : (seg == 1) ? key : value;
    const float* W = ipw + (long)seg * E_DIM * E_DIM;
    const float* bias = ipb + seg * E_DIM;
    float* C = (seg == 0) ? Qo : (seg == 1) ? Ko : Vo;
    const float alpha = (seg == 0) ? 0.125f : 1.0f;

    GEMM_DB_CORE(A, W)
    GEMM_EPILOGUE(C, bias, alpha)
}

// ---------------------------------------------------------------------------
// Output projection
// ---------------------------------------------------------------------------
__global__ void __launch_bounds__(256) gemm_out(
    const float* __restrict__ Ain, const float* __restrict__ W,
    const float* __restrict__ bias, float* __restrict__ C)
{
    GEMM_PROLOGUE
    const int m0 = blockIdx.y * 128, n0 = blockIdx.x * 128;

    GEMM_DB_CORE(Ain, W)
    GEMM_EPILOGUE(C, bias, 1.0f)
}

// ---------------------------------------------------------------------------
// Score kernel — frag-interleaved + rotation (R12 verbatim).
// ---------------------------------------------------------------------------
#define SCORE_SMEM_BYTES (16384 * 4)

__global__ void __launch_bounds__(256) score_kernel(
    const float* __restrict__ Q, const float* __restrict__ Kx,
    const float* __restrict__ amask, const int* __restrict__ pad,
    float* __restrict__ Sc)
{
    extern __shared__ uint32_t dsm[];
    uint32_t* As = dsm;                 // 8192 words
    uint32_t* Bs = dsm + 8192;          // 8192 words
    const int tid = threadIdx.x, lane = tid & 31, wid = tid >> 5;
    const int wm = (wid >> 2) * 64, wn = (wid & 3) * 32;
    const int wmb = wm >> 4, wnb = wn >> 3;
    const int t0 = blockIdx.y * 128, s0 = blockIdx.x * 128;
    const int z = blockIdx.z;
    const int b = z >> 4, h = z & 15;
    const int g = lane >> 2, tg = lane & 3;
    const float* Qb = Q + (long)b * E_DIM + h * D_DIM;
    const float* Kb = Kx + (long)b * E_DIM + h * D_DIM;

    float acc[4][4][4];
    #pragma unroll
    for (int i = 0; i < 4; i++)
        #pragma unroll
        for (int j = 0; j < 4; j++)
            #pragma unroll
            for (int q = 0; q < 4; q++) acc[i][j][q] = 0.f;

    {
        const int srow = tid >> 3;            // 0..31 (+pr*32)
        const int skc = (tid & 7) << 2;       // 0,4,...,28 (+pk*32)
        #pragma unroll
        for (int pr = 0; pr < 4; pr++) {
            int row = srow + pr * 32;
            int mbq = row >> 4, fragm = ((row & 15) >= 8) ? 1 : 0;
            int nb8 = row >> 3;
            int laneb = (row & 7) * 4;
            #pragma unroll
            for (int pk = 0; pk < 2; pk++) {
                int kc = skc + pk * 32;
                int sb = kc >> 3;
                int fragk2 = ((kc & 7) >= 4) ? 2 : 0;
                int fb = ((kc & 7) >= 4) ? 1 : 0;
                int R = (row + sb) & 3;
                float4 q4 = *(const float4*)(Qb + (long)(t0 + row) * BE + kc);
                float4 k4 = *(const float4*)(Kb + (long)(s0 + row) * BE + kc);
                uint32_t* aw = As + ((sb * 8 + mbq) * 32 + laneb) * 4 + fragk2 + fragm;
                uint32_t* bw = Bs + ((sb * 16 + nb8) * 32 + laneb) * 2 + fb;
                aw[4 * ((0 + R) & 3)] = f2tf(q4.x);
                aw[4 * ((1 + R) & 3)] = f2tf(q4.y);
                aw[4 * ((2 + R) & 3)] = f2tf(q4.z);
                aw[4 * ((3 + R) & 3)] = f2tf(q4.w);
                bw[2 * ((0 + R) & 3)] = f2tf(k4.x);
                bw[2 * ((1 + R) & 3)] = f2tf(k4.y);
                bw[2 * ((2 + R) & 3)] = f2tf(k4.z);
                bw[2 * ((3 + R) & 3)] = f2tf(k4.w);
            }
        }
    }
    __syncthreads();

    #pragma unroll
    for (int sb = 0; sb < 8; sb++) {
        const int sw = (g << 2) + ((tg + g + sb) & 3);
        uint4 af[4];
        uint2 bf[4];
        #pragma unroll
        for (int mt = 0; mt < 4; mt++)
            af[mt] = *(const uint4*)(As + ((sb * 8 + wmb + mt) * 32 + sw) * 4);
        #pragma unroll
        for (int nt = 0; nt < 4; nt++)
            bf[nt] = *(const uint2*)(Bs + ((sb * 16 + wnb + nt) * 32 + sw) * 2);
        #pragma unroll
        for (int mt = 0; mt < 4; mt++)
            #pragma unroll
            for (int nt = 0; nt < 4; nt++)
                mma8(acc[mt][nt], (const uint32_t*)&af[mt], (const uint32_t*)&bf[nt]);
    }

    float* So = Sc + (long)z * T_DIM * S_DIM;
    #pragma unroll
    for (int mt = 0; mt < 4; mt++) {
        int t = t0 + wm + mt * 16 + g;
        #pragma unroll
        for (int nt = 0; nt < 4; nt++) {
            int s = s0 + wn + nt * 8 + 2 * tg;
            float p0 = pad[b * S_DIM + s]     ? -1e30f : 0.f;
            float p1 = pad[b * S_DIM + s + 1] ? -1e30f : 0.f;
            float2 a0 = *(const float2*)(amask + (long)t * S_DIM + s);
            float2 a1 = *(const float2*)(amask + (long)(t + 8) * S_DIM + s);
            float2 o0, o1;
            o0.x = acc[mt][nt][0] + a0.x + p0;
            o0.y = acc[mt][nt][1] + a0.y + p1;
            o1.x = acc[mt][nt][2] + a1.x + p0;
            o1.y = acc[mt][nt][3] + a1.y + p1;
            *(float2*)(So + (long)t * S_DIM + s) = o0;
            *(float2*)(So + (long)(t + 8) * S_DIM + s) = o1;
        }
    }
}

// ---------------------------------------------------------------------------
// Softmax + head-average (verbatim): block = (b,t), 16 warps = 16 heads.
// ---------------------------------------------------------------------------
#define SA_SMEM_BYTES (H_DIM * S_DIM * 4)   // 65536

__global__ void __launch_bounds__(512) softmax_avg(
    float* __restrict__ P, float* __restrict__ avgw)
{
    extern __shared__ float Ps[];            // [16][1024]
    const int bid = blockIdx.x;
    const int b = bid >> 10, t = bid & 1023;
    const int h = threadIdx.x >> 5, lane = threadIdx.x & 31;

    float4* p = (float4*)(P + (((long)(b * H_DIM + h) * T_DIM) + t) * S_DIM);
    float4 v[8];
    float m = -1e30f;
    #pragma unroll
    for (int i = 0; i < 8; i++) {
        v[i] = p[lane + 32 * i];
        m = fmaxf(m, fmaxf(fmaxf(v[i].x, v[i].y), fmaxf(v[i].z, v[i].w)));
    }
    #pragma unroll
    for (int o = 16; o; o >>= 1) m = fmaxf(m, __shfl_xor_sync(0xffffffffu, m, o));
    float sum = 0.f;
    #pragma unroll
    for (int i = 0; i < 8; i++) {
        v[i].x = __expf(v[i].x - m); v[i].y = __expf(v[i].y - m);
        v[i].z = __expf(v[i].z - m); v[i].w = __expf(v[i].w - m);
        sum += v[i].x + v[i].y + v[i].z + v[i].w;
    }
    #pragma unroll
    for (int o = 16; o; o >>= 1) sum += __shfl_xor_sync(0xffffffffu, sum, o);
    float inv = 1.0f / sum;
    float4* ps = (float4*)(Ps + h * S_DIM);
    #pragma unroll
    for (int i = 0; i < 8; i++) {
        v[i].x *= inv; v[i].y *= inv; v[i].z *= inv; v[i].w *= inv;
        p[lane + 32 * i] = v[i];
        ps[lane + 32 * i] = v[i];
    }
    __syncthreads();

    int s2 = threadIdx.x * 2;
    float a0 = 0.f, a1 = 0.f;
    #pragma unroll
    for (int hh = 0; hh < H_DIM; hh++) {
        float2 pv = *(const float2*)(Ps + hh * S_DIM + s2);
        a0 += pv.x; a1 += pv.y;
    }
    const float inv16 = 1.0f / H_DIM;
    *(float2*)(avgw + ((long)b * T_DIM + t) * S_DIM + s2) =
        make_float2(a0 * inv16, a1 * inv16);
}

// ---------------------------------------------------------------------------
// PV — A (P matrix) in frag-interleaved + rotation layout; B simple (R11).
// Per stage: A = 4 slabs x 8 mb = 4096 w (x2), B = [PBK][VLDB] (x2).
// ---------------------------------------------------------------------------
#define VLDB 72
#define PV_SMEM_WORDS (2 * 4096 + 2 * PBK * VLDB)   // 8192 + 4608 = 12800
#define PV_SMEM_BYTES (PV_SMEM_WORDS * 4)           // 51200

__global__ void __launch_bounds__(256) pv_kernel(
    const float* __restrict__ Sc, const float* __restrict__ V,
    float* __restrict__ Ctx)
{
    extern __shared__ uint32_t dsm[];
    uint32_t* Asm = dsm;            // 2 stages x 4096 (frag layout)
    uint32_t* Bsm = dsm + 8192;     // [2*PBK][VLDB]
    const int tid = threadIdx.x, lane = tid & 31, wid = tid >> 5;
    const int wm = (wid >> 1) * 32, wn = (wid & 1) * 32;
    const int wmb = wm >> 4;
    const int t0 = blockIdx.x * 128;
    const int z = blockIdx.z;
    const int b = z >> 4, h = z & 15;
    const int g = lane >> 2, tg = lane & 3;
    const float* Pb = Sc + (long)z * T_DIM * S_DIM;
    const float* Vb = V + (long)b * E_DIM + h * D_DIM;

    float acc[2][4][4];
    #pragma unroll
    for (int i = 0; i < 2; i++)
        #pragma unroll
        for (int j = 0; j < 4; j++)
            #pragma unroll
            for (int q = 0; q < 4; q++) acc[i][j][q] = 0.f;

    // A staging: rows arow + p*32, k-float4 at akc
    const int arow = tid >> 3, akc = (tid & 7) << 2;
    const int asb = akc >> 3;
    const int afragk2 = ((akc & 7) >= 4) ? 2 : 0;
    // B staging: k-rows bs_s + p*16, n-float4 at bs_d
    const int bs_s = tid >> 4, bs_d = (tid & 15) << 2;

    float4 pa[4], pv[2];
    #pragma unroll
    for (int p = 0; p < 4; p++)
        pa[p] = *(const float4*)(Pb + (long)(t0 + arow + p * 32) * S_DIM + akc);
    #pragma unroll
    for (int p = 0; p < 2; p++)
        pv[p] = *(const float4*)(Vb + (long)(bs_s + p * 16) * BE + bs_d);

#define PV_ASTAGE(AOFF)                                                       \
    _Pragma("unroll")                                                         \
    for (int p = 0; p < 4; p++) {                                             \
        int row = arow + p * 32;                                              \
        int mbq = row >> 4, fragm = ((row & 15) >= 8) ? 1 : 0;                \
        int laneb = (row & 7) * 4;                                            \
        int R = (row + asb) & 3;                                              \
        uint32_t* aw = Asm + (AOFF) + ((asb * 8 + mbq) * 32 + laneb) * 4      \
                       + afragk2 + fragm;                                     \
        aw[4 * ((0 + R) & 3)] = f2tf(pa[p].x);                                \
        aw[4 * ((1 + R) & 3)] = f2tf(pa[p].y);                                \
        aw[4 * ((2 + R) & 3)] = f2tf(pa[p].z);                                \
        aw[4 * ((3 + R) & 3)] = f2tf(pa[p].w);                                \
    }

#define PV_BSTAGE(BROW)                                                       \
    _Pragma("unroll")                                                         \
    for (int p = 0; p < 2; p++) {                                             \
        int s = bs_s + p * 16;                                                \
        Bsm[((BROW) + s) * VLDB + bs_d + 0] = f2tf(pv[p].x);                  \
        Bsm[((BROW) + s) * VLDB + bs_d + 1] = f2tf(pv[p].y);                  \
        Bsm[((BROW) + s) * VLDB + bs_d + 2] = f2tf(pv[p].z);                  \
        Bsm[((BROW) + s) * VLDB + bs_d + 3] = f2tf(pv[p].w);                  \
    }

    PV_ASTAGE(0)
    PV_BSTAGE(0)

    for (int it = 0; it < S_DIM / PBK; it++) {
        const int curA = (it & 1) * 4096;
        const int curB = (it & 1) * PBK;
        __syncthreads();
        if (it < S_DIM / PBK - 1) {
            int k0 = (it + 1) * PBK;
            #pragma unroll
            for (int p = 0; p < 4; p++)
                pa[p] = *(const float4*)(Pb + (long)(t0 + arow + p * 32) * S_DIM + k0 + akc);
            #pragma unroll
            for (int p = 0; p < 2; p++)
                pv[p] = *(const float4*)(Vb + (long)(k0 + bs_s + p * 16) * BE + bs_d);
        }
        #pragma unroll
        for (int ks = 0; ks < PBK; ks += 8) {
            const int sb = ks >> 3;
            const int sw = (g << 2) + ((tg + g + sb) & 3);
            uint4 af[2];
            uint32_t bf[4][2];
            #pragma unroll
            for (int mt = 0; mt < 2; mt++)
                af[mt] = *(const uint4*)(Asm + curA + ((sb * 8 + wmb + mt) * 32 + sw) * 4);
            #pragma unroll
            for (int nt = 0; nt < 4; nt++) {
                int n = wn + nt * 8 + g;
                bf[nt][0] = Bsm[(curB + ks + tg) * VLDB + n];
                bf[nt][1] = Bsm[(curB + ks + tg + 4) * VLDB + n];
            }
            #pragma unroll
            for (int mt = 0; mt < 2; mt++)
                #pragma unroll
                for (int nt = 0; nt < 4; nt++)
                    mma8(acc[mt][nt], (const uint32_t*)&af[mt], bf[nt]);
        }
        if (it < S_DIM / PBK - 1) {
            PV_ASTAGE(((it + 1) & 1) * 4096)
            PV_BSTAGE(((it + 1) & 1) * PBK)
        }
    }

    #pragma unroll
    for (int mt = 0; mt < 2; mt++) {
        int t = t0 + wm + mt * 16 + g;
        #pragma unroll
        for (int nt = 0; nt < 4; nt++) {
            int d = wn + nt * 8 + 2 * tg;
            *(float2*)(Ctx + (long)t * BE + b * E_DIM + h * D_DIM + d) =
                make_float2(acc[mt][nt][0], acc[mt][nt][1]);
            *(float2*)(Ctx + (long)(t + 8) * BE + b * E_DIM + h * D_DIM + d) =
                make_float2(acc[mt][nt][2], acc[mt][nt][3]);
        }
    }
}

// ---------------------------------------------------------------------------
extern "C" void kernel_launch(void* const* d_in, const int* in_sizes, int n_in,
                              void* d_out, int out_size) {
    const float* query = (const float*)d_in[0];
    const float* key   = (const float*)d_in[1];
    const float* value = (const float*)d_in[2];
    const int*   pad   = (const int*)d_in[3];
    const float* amask = (const float*)d_in[4];
    const float* ipw   = (const float*)d_in[5];
    const float* ipb   = (const float*)d_in[6];
    const float* ow    = (const float*)d_in[7];
    const float* ob    = (const float*)d_in[8];

    float* out  = (float*)d_out;
    float* avgw = out + (long)T_DIM * B_DIM * E_DIM;

    float *Qp, *Kp, *Vp, *Cp, *Pp;
    cudaGetSymbolAddress((void**)&Qp, g_Q);
    cudaGetSymbolAddress((void**)&Kp, g_K);
    cudaGetSymbolAddress((void**)&Vp, g_V);
    cudaGetSymbolAddress((void**)&Cp, g_Ctx);
    cudaGetSymbolAddress((void**)&Pp, g_P);

    cudaFuncSetAttribute(gemm_qkv,
        cudaFuncAttributeMaxDynamicSharedMemorySize, GEMM_SMEM_BYTES);
    cudaFuncSetAttribute(gemm_out,
        cudaFuncAttributeMaxDynamicSharedMemorySize, GEMM_SMEM_BYTES);
    cudaFuncSetAttribute(score_kernel,
        cudaFuncAttributeMaxDynamicSharedMemorySize, SCORE_SMEM_BYTES);
    cudaFuncSetAttribute(softmax_avg,
        cudaFuncAttributeMaxDynamicSharedMemorySize, SA_SMEM_BYTES);
    cudaFuncSetAttribute(pv_kernel,
        cudaFuncAttributeMaxDynamicSharedMemorySize, PV_SMEM_BYTES);

    gemm_qkv<<<dim3(24, 32), 256, GEMM_SMEM_BYTES>>>(
        query, key, value, ipw, ipb, Qp, Kp, Vp);

    score_kernel<<<dim3(8, 8, 64), 256, SCORE_SMEM_BYTES>>>(
        Qp, Kp, amask, pad, Pp);

    softmax_avg<<<B_DIM * T_DIM, 512, SA_SMEM_BYTES>>>(Pp, avgw);

    pv_kernel<<<dim3(8, 1, 64), 256, PV_SMEM_BYTES>>>(Pp, Vp, Cp);

    gemm_out<<<dim3(8, 32), 256, GEMM_SMEM_BYTES>>>(Cp, ow, ob, out);
}